// round 9
// baseline (speedup 1.0000x reference)
#include <cuda_runtime.h>
#include <cuda_bf16.h>
#include <cstdint>

#define B_     32
#define TENC   512
#define TDEC   32
#define DIM    256
#define VOCAB_ 32000
#define SOS_   1

// ---------------- device scratch ----------------
__device__ float g_encWm[B_ * TENC * DIM];   // enc@Wm.T + bm
__device__ float g_encWc[B_ * TENC * DIM];   // enc@Wc.T + bc
__device__ float g_hVm[B_ * DIM];
__device__ float g_hVc[B_ * DIM];
__device__ float g_p[B_ * TENC];
__device__ float g_ecb[B_ * TENC];
__device__ float g_attn[TDEC * B_ * DIM];    // row = t*B + b
__device__ float g_WrT[512 * 256];           // [k][o]: k<256 -> W_ih[o][k], else W_hh
__device__ float g_WcombT[512 * 256];        // [k][o] = W_comb[o][k]
__device__ float g_VT2[256 * 512];           // [k][o]: o<256 -> Vm[o][k], else Vc
__device__ float g_biasr[256];               // b_ih + b_hh
__device__ float g_wm[256];
__device__ float g_wc[256];
__device__ float g_cst[2];
__device__ unsigned g_hv[B_];                // hV generation per batch
__device__ unsigned g_ecnt[B_];              // energy arrivals per batch (3/step)

// ---------------- helpers ----------------
__device__ __forceinline__ float warp_sum(float v) {
#pragma unroll
    for (int s = 16; s; s >>= 1) v += __shfl_xor_sync(0xffffffffu, v, s);
    return v;
}
__device__ __forceinline__ float tanh_fast(float x) {
    float e = __expf(2.0f * x);
    return 1.0f - __fdividef(2.0f, e + 1.0f);
}
__device__ __forceinline__ float sigmoid_fast(float x) {
    return __fdividef(1.0f, 1.0f + __expf(-x));
}

// exclusive prefix over 256 per-thread pair-sums
__device__ __forceinline__ float pair_excl(float ps, float* s_w8) {
    int tid = threadIdx.x, lane = tid & 31, wid = tid >> 5;
    float s = ps;
#pragma unroll
    for (int d = 1; d < 32; d <<= 1) {
        float n = __shfl_up_sync(0xffffffffu, s, d);
        if (lane >= d) s += n;
    }
    __syncthreads();
    if (lane == 31) s_w8[wid] = s;
    __syncthreads();
    if (tid < 32) {
        float v = (lane < 8) ? s_w8[lane] : 0.0f;
#pragma unroll
        for (int d = 1; d < 8; d <<= 1) {
            float n = __shfl_up_sync(0xffffffffu, v, d);
            if (lane >= d) v += n;
        }
        if (lane < 8) s_w8[lane] = v;
    }
    __syncthreads();
    float woff = wid ? s_w8[wid - 1] : 0.0f;
    return woff + (s - ps);
}

__device__ __forceinline__ float max512(float m, float* s_w8) {
    int tid = threadIdx.x, lane = tid & 31, wid = tid >> 5;
#pragma unroll
    for (int s = 16; s; s >>= 1) m = fmaxf(m, __shfl_xor_sync(0xffffffffu, m, s));
    __syncthreads();
    if (lane == 0) s_w8[wid] = m;
    __syncthreads();
    if (tid < 32) {
        float v = (lane < 8) ? s_w8[lane] : -1e30f;
#pragma unroll
        for (int s = 4; s; s >>= 1) v = fmaxf(v, __shfl_xor_sync(0xffffffffu, v, s));
        if (lane == 0) s_w8[0] = v;
    }
    __syncthreads();
    return s_w8[0];
}

// y[o=tid] = sum_k x[k] * WT[k*256+o]
template <int K>
__device__ __forceinline__ float gemvT256(const float* __restrict__ WT,
                                          const float* __restrict__ x, float* s_part) {
    int tid = threadIdx.x;
    int j = tid & 63, kq = tid >> 6;
    __syncthreads();
    const float4* Wp = reinterpret_cast<const float4*>(WT);
    float4 acc = make_float4(0.f, 0.f, 0.f, 0.f);
    int k0 = kq * (K / 4);
#pragma unroll 8
    for (int k = k0; k < k0 + K / 4; ++k) {
        float f = x[k];
        float4 w = Wp[(size_t)k * 64 + j];
        acc.x = fmaf(f, w.x, acc.x);
        acc.y = fmaf(f, w.y, acc.y);
        acc.z = fmaf(f, w.z, acc.z);
        acc.w = fmaf(f, w.w, acc.w);
    }
    reinterpret_cast<float4*>(s_part)[kq * 64 + j] = acc;
    __syncthreads();
    return s_part[tid] + s_part[256 + tid] + s_part[512 + tid] + s_part[768 + tid];
}

// hV = h @ [Vm|Vc]^T -> g_hVm/g_hVc via stcg
__device__ __forceinline__ void gemv_hv(int b, const float* __restrict__ x, float* s_part) {
    int tid = threadIdx.x;
    int j = tid & 127, kh = tid >> 7;
    __syncthreads();
    const float4* Wp = reinterpret_cast<const float4*>(g_VT2);
    float4 acc = make_float4(0.f, 0.f, 0.f, 0.f);
    int k0 = kh * 128;
#pragma unroll 8
    for (int k = k0; k < k0 + 128; ++k) {
        float f = x[k];
        float4 w = Wp[(size_t)k * 128 + j];
        acc.x = fmaf(f, w.x, acc.x);
        acc.y = fmaf(f, w.y, acc.y);
        acc.z = fmaf(f, w.z, acc.z);
        acc.w = fmaf(f, w.w, acc.w);
    }
    reinterpret_cast<float4*>(s_part)[kh * 128 + j] = acc;
    __syncthreads();
    __stcg(&g_hVm[b * DIM + tid], s_part[tid] + s_part[512 + tid]);
    __stcg(&g_hVc[b * DIM + tid], s_part[256 + tid] + s_part[768 + tid]);
}

// h' = tanh([emb[tok], h] @ [W_ih|W_hh]^T + bias); then hV projections
__device__ __forceinline__ void rnn_hv(int b, int tok, const float* __restrict__ emb,
                                       float* s_xh, float* s_part, float* s_h) {
    int tid = threadIdx.x;
    __syncthreads();
    s_xh[tid] = __ldg(&emb[(size_t)tok * DIM + tid]);
    s_xh[256 + tid] = s_h[tid];
    float a = gemvT256<512>(g_WrT, s_xh, s_part) + g_biasr[tid];
    float hn = tanh_fast(a);
    __syncthreads();
    s_h[tid] = hn;
    gemv_hv(b, s_h, s_part);
}

// publish: stores (already issued per-thread) -> fence -> barrier -> single atomic
__device__ __forceinline__ void publish_exch(unsigned* flag, unsigned v) {
    __threadfence();
    __syncthreads();
    if (threadIdx.x == 0) atomicExch(flag, v);
}
__device__ __forceinline__ void publish_add(unsigned* flag) {
    __threadfence();
    __syncthreads();
    if (threadIdx.x == 0) atomicAdd(flag, 1u);
}
__device__ __forceinline__ void spin_ge(const unsigned* flag, unsigned v) {
    const volatile unsigned* f = (const volatile unsigned*)flag;
    while (*f < v) {}
    __threadfence();
}

// energy for quarter q of batch b at step t; per-thread register slices of hV/w
__device__ __forceinline__ void energy_quarter(int b, int q, int t,
                                               const float* __restrict__ noise,
                                               const float* rhm, const float* rhc,
                                               const float* rwm, const float* rwc,
                                               float cm, float cc) {
    int tid = threadIdx.x, wid = tid >> 5, lane = tid & 31;
    int tt0 = q * 128 + wid * 16;
    const size_t base = (size_t)b * TENC;
#pragma unroll 1
    for (int i2 = 0; i2 < 16; ++i2) {
        int tt = tt0 + i2;
        const float4* em4 = reinterpret_cast<const float4*>(g_encWm + (base + tt) * DIM) +
                            lane * 2;
        const float4* ec4 = reinterpret_cast<const float4*>(g_encWc + (base + tt) * DIM) +
                            lane * 2;
        float4 m0 = em4[0], m1 = em4[1];
        float4 c0 = ec4[0], c1 = ec4[1];
        float mv[8] = {m0.x, m0.y, m0.z, m0.w, m1.x, m1.y, m1.z, m1.w};
        float cv[8] = {c0.x, c0.y, c0.z, c0.w, c1.x, c1.y, c1.z, c1.w};
        float am = 0.f, ac = 0.f;
#pragma unroll
        for (int j = 0; j < 8; ++j) {
            am = fmaf(tanh_fast(mv[j] + rhm[j]), rwm[j], am);
            ac = fmaf(tanh_fast(cv[j] + rhc[j]), rwc[j], ac);
        }
        am = warp_sum(am);
        ac = warp_sum(ac);
        if (lane == 0) {
            float pp = sigmoid_fast(am + cm +
                                    __ldg(&noise[((size_t)t * B_ + b) * TENC + tt]));
            __stcg(&g_p[b * TENC + tt], pp);
            __stcg(&g_ecb[b * TENC + tt], ac + cc);
        }
    }
}

// ---------------- init: weight transposes, weight-norm, biases, flag reset -------------
__global__ void k_init(const float* __restrict__ W_ih, const float* __restrict__ b_ih,
                       const float* __restrict__ W_hh, const float* __restrict__ b_hh,
                       const float* __restrict__ Vm, const float* __restrict__ Vc,
                       const float* __restrict__ W_comb,
                       const float* __restrict__ vvm, const float* __restrict__ gm,
                       const float* __restrict__ vbm, const float* __restrict__ rm,
                       const float* __restrict__ vvc, const float* __restrict__ gc,
                       const float* __restrict__ vbc, const float* __restrict__ rc) {
    int bidx = blockIdx.x, tid = threadIdx.x;
    if (bidx < 64) {
        for (int idx = bidx * 256 + tid; idx < 393216; idx += 64 * 256) {
            if (idx < 131072) {
                int k = idx >> 8, o = idx & 255;
                g_WrT[idx] = (k < 256) ? W_ih[o * 256 + k] : W_hh[o * 256 + (k - 256)];
            } else if (idx < 262144) {
                int r = idx - 131072;
                int k = r >> 8, o = r & 255;
                g_WcombT[r] = W_comb[o * 512 + k];
            } else {
                int r = idx - 262144;
                int k = r >> 9, o = r & 511;
                g_VT2[r] = (o < 256) ? Vm[o * 256 + k] : Vc[(o - 256) * 256 + k];
            }
        }
    } else {
        __shared__ float red[256];
        if (tid < 32) {
            g_hv[tid] = 0u;
            g_ecnt[tid] = 0u;
        }
        float v = vvm[tid];
        red[tid] = v * v;
        __syncthreads();
        for (int s = 128; s > 0; s >>= 1) {
            if (tid < s) red[tid] += red[tid + s];
            __syncthreads();
        }
        float nm = sqrtf(red[0]);
        __syncthreads();
        g_wm[tid] = vvm[tid] * gm[0] / nm;
        float v2 = vvc[tid];
        red[tid] = v2 * v2;
        __syncthreads();
        for (int s = 128; s > 0; s >>= 1) {
            if (tid < s) red[tid] += red[tid + s];
            __syncthreads();
        }
        float nc = sqrtf(red[0]);
        __syncthreads();
        g_wc[tid] = vvc[tid] * gc[0] / nc;
        g_biasr[tid] = b_ih[tid] + b_hh[tid];
        if (tid == 0) {
            g_cst[0] = vbm[0] + rm[0];
            g_cst[1] = vbc[0] + rc[0];
        }
    }
}

// ---------------- persistent step kernel: decoupled per-batch pipelines ----------------
// CTA roles: b = cta&31, q = cta>>5. q==0 CTAs additionally run the post phase for b.
__global__ __launch_bounds__(256, 1) void k_steps(const float* __restrict__ enc,
                                                  const int* __restrict__ dec,
                                                  const float* __restrict__ h0,
                                                  const float* __restrict__ noise,
                                                  const float* __restrict__ emb) {
    __shared__ float s_alpha[512];
    __shared__ float s_h[256];
    __shared__ float s_eu[512];
    __shared__ float s_ratio[512];
    __shared__ float s_beta[512];
    __shared__ float s_xh[512];
    __shared__ float s_part[1024];
    __shared__ float s_w8[32];

    int tid = threadIdx.x, cta = blockIdx.x;
    int b = cta & 31, q = cta >> 5;
    bool is_post = (q == 0);
    int lane = tid & 31;
    int a0 = lane * 8;

    float cm = g_cst[0], cc = g_cst[1];
    // register-resident weight-norm vectors (per-lane slice, same for all warps)
    float rwm[8], rwc[8];
#pragma unroll
    for (int j = 0; j < 8; ++j) {
        rwm[j] = __ldg(&g_wm[a0 + j]);
        rwc[j] = __ldg(&g_wc[a0 + j]);
    }

    if (is_post) {
        s_h[tid] = h0[b * DIM + tid];
        s_alpha[tid] = (tid == 0) ? 1.0f : 0.0f;
        s_alpha[256 + tid] = 0.0f;
        rnn_hv(b, SOS_, emb, s_xh, s_part, s_h);
        publish_exch(&g_hv[b], 1u);
    }

#pragma unroll 1
    for (int t = 0; t < TDEC; ++t) {
        // wait for hV of step t (post CTA passes immediately: it just published)
        spin_ge(&g_hv[b], (unsigned)(t + 1));
        float rhm[8], rhc[8];
        {
            float4 h0v = __ldcg(reinterpret_cast<const float4*>(g_hVm + b * DIM + a0));
            float4 h1v = __ldcg(reinterpret_cast<const float4*>(g_hVm + b * DIM + a0 + 4));
            rhm[0] = h0v.x; rhm[1] = h0v.y; rhm[2] = h0v.z; rhm[3] = h0v.w;
            rhm[4] = h1v.x; rhm[5] = h1v.y; rhm[6] = h1v.z; rhm[7] = h1v.w;
            float4 c0v = __ldcg(reinterpret_cast<const float4*>(g_hVc + b * DIM + a0));
            float4 c1v = __ldcg(reinterpret_cast<const float4*>(g_hVc + b * DIM + a0 + 4));
            rhc[0] = c0v.x; rhc[1] = c0v.y; rhc[2] = c0v.z; rhc[3] = c0v.w;
            rhc[4] = c1v.x; rhc[5] = c1v.y; rhc[6] = c1v.z; rhc[7] = c1v.w;
        }
        energy_quarter(b, q, t, noise, rhm, rhc, rwm, rwc, cm, cc);

        if (!is_post) {
            publish_add(&g_ecnt[b]);
            continue;
        }
        __threadfence();
        __syncthreads();  // own-quarter writes visible intra-CTA
        // wait for the other 3 quarters
        spin_ge(&g_ecnt[b], 3u * (unsigned)(t + 1));

        // ---- post phase ----
        int j0 = 2 * tid, j1 = 2 * tid + 1;
        float p0 = __ldcg(&g_p[b * TENC + j0]);
        float p1 = __ldcg(&g_p[b * TENC + j1]);
        float l0 = __logf(fminf(fmaxf(1.0f - p0, 1e-10f), 1.0f));
        float l1 = __logf(fminf(fmaxf(1.0f - p1, 1e-10f), 1.0f));
        float eP = pair_excl(l0 + l1, s_w8);
        float cp0 = __expf(eP);
        float cp1 = __expf(eP + l0);
        float A0 = s_alpha[j0], A1 = s_alpha[j1];
        float r0 = __fdividef(A0, fmaxf(cp0, 1e-10f));
        float r1 = __fdividef(A1, fmaxf(cp1, 1e-10f));
        float eS = pair_excl(r0 + r1, s_w8);
        float na0 = p0 * cp0 * (eS + r0);
        float na1 = p1 * cp1 * (eS + r0 + r1);
        s_alpha[j0] = na0;
        s_alpha[j1] = na1;

        // chunkwise beta
        float e0 = __ldcg(&g_ecb[b * TENC + j0]);
        float e1 = __ldcg(&g_ecb[b * TENC + j1]);
        float mx = max512(fmaxf(e0, e1), s_w8);
        float eu0 = __expf(e0 - mx), eu1 = __expf(e1 - mx);
        s_eu[j0] = eu0;
        s_eu[j1] = eu1;
        __syncthreads();
        float d0 = 0.0f, d1 = 0.0f;
#pragma unroll
        for (int k = 0; k < 8; ++k) {
            int q0 = j0 - k, q1 = j1 - k;
            if (q0 >= 0) d0 += s_eu[q0];
            if (q1 >= 0) d1 += s_eu[q1];
        }
        s_ratio[j0] = __fdividef(na0, fmaxf(d0, 1e-10f));
        s_ratio[j1] = __fdividef(na1, fmaxf(d1, 1e-10f));
        __syncthreads();
        float b0 = 0.0f, b1 = 0.0f;
#pragma unroll
        for (int k = 0; k < 8; ++k) {
            int q0 = j0 + k, q1 = j1 + k;
            if (q0 < TENC) b0 += s_ratio[q0];
            if (q1 < TENC) b1 += s_ratio[q1];
        }
        s_beta[j0] = eu0 * b0;
        s_beta[j1] = eu1 * b1;
        __syncthreads();

        // context = beta @ enc[b]
        {
            int jj = tid & 63, tq4 = tid >> 6;
            const float4* ep = reinterpret_cast<const float4*>(enc) +
                               (size_t)(b * TENC + tq4 * 128) * (DIM / 4) + jj;
            float4 acc = make_float4(0.f, 0.f, 0.f, 0.f);
#pragma unroll 4
            for (int ttt = 0; ttt < 128; ++ttt) {
                float f = s_beta[tq4 * 128 + ttt];
                float4 e4 = ep[(size_t)ttt * 64];
                acc.x = fmaf(f, e4.x, acc.x);
                acc.y = fmaf(f, e4.y, acc.y);
                acc.z = fmaf(f, e4.z, acc.z);
                acc.w = fmaf(f, e4.w, acc.w);
            }
            reinterpret_cast<float4*>(s_part)[tq4 * 64 + jj] = acc;
        }
        __syncthreads();
        s_xh[tid] = s_part[tid] + s_part[256 + tid] + s_part[512 + tid] + s_part[768 + tid];
        s_xh[256 + tid] = s_h[tid];

        // attn = tanh([ctx, h] @ W_comb.T)
        float av = gemvT256<512>(g_WcombT, s_xh, s_part);
        __stcg(&g_attn[((size_t)t * B_ + b) * DIM + tid], tanh_fast(av));

        // next hidden state + hV (token for step t+1)
        rnn_hv(b, __ldg(&dec[b * TDEC + t]), emb, s_xh, s_part, s_h);
        publish_exch(&g_hv[b], (unsigned)(t + 2));
    }
}

// ---------------- SGEMM: C = A @ B^T + bias (f32x2 packed FMA) ----------------
__device__ __forceinline__ unsigned long long pack2(float x) {
    unsigned long long r;
    asm("mov.b64 %0, {%1, %1};" : "=l"(r) : "f"(x));
    return r;
}
__device__ __forceinline__ void fma2(unsigned long long& acc, unsigned long long a,
                                     unsigned long long b) {
    asm("fma.rn.f32x2 %0, %1, %2, %0;" : "+l"(acc) : "l"(a), "l"(b));
}
__device__ __forceinline__ void unpack2(unsigned long long v, float& lo, float& hi) {
    asm("mov.b64 {%0, %1}, %2;" : "=f"(lo), "=f"(hi) : "l"(v));
}

template <bool REMAP>
__global__ __launch_bounds__(256, 2) void gemm_tn(const float* __restrict__ A,
                                                  const float* __restrict__ Bw,
                                                  const float* __restrict__ bias,
                                                  float* __restrict__ C, int M, int N,
                                                  int K) {
    __shared__ __align__(16) float As[8][128];
    __shared__ __align__(16) float Bs[8][128];
    int tid = threadIdx.x;
    int tx = tid & 15, ty = tid >> 4;
    int bm = blockIdx.y * 128, bn = blockIdx.x * 128;
    int lrow = tid >> 1;
    int lk = (tid & 1) * 4;

    unsigned long long acc[8][4] = {};
    const float* Aptr = A + (size_t)(bm + lrow) * K + lk;
    const float* Bptr = Bw + (size_t)(bn + lrow) * K + lk;

    for (int k0 = 0; k0 < K; k0 += 8) {
        float4 av = *reinterpret_cast<const float4*>(Aptr + k0);
        float4 bv = *reinterpret_cast<const float4*>(Bptr + k0);
        As[lk + 0][lrow] = av.x;
        As[lk + 1][lrow] = av.y;
        As[lk + 2][lrow] = av.z;
        As[lk + 3][lrow] = av.w;
        Bs[lk + 0][lrow] = bv.x;
        Bs[lk + 1][lrow] = bv.y;
        Bs[lk + 2][lrow] = bv.z;
        Bs[lk + 3][lrow] = bv.w;
        __syncthreads();
#pragma unroll
        for (int kk = 0; kk < 8; ++kk) {
            const float4* arow4 = reinterpret_cast<const float4*>(&As[kk][ty * 8]);
            const float4* brow4 = reinterpret_cast<const float4*>(&Bs[kk][tx * 8]);
            float4 af0 = arow4[0], af1 = arow4[1];
            float4 bf0 = brow4[0], bf1 = brow4[1];
            float ar[8] = {af0.x, af0.y, af0.z, af0.w, af1.x, af1.y, af1.z, af1.w};
            unsigned long long b2[4];
            b2[0] = pack2(bf0.x);  // placeholder, replaced below
            // pack b pairs: (bf0.x,bf0.y),(bf0.z,bf0.w),(bf1.x,bf1.y),(bf1.z,bf1.w)
            asm("mov.b64 %0, {%1, %2};" : "=l"(b2[0]) : "f"(bf0.x), "f"(bf0.y));
            asm("mov.b64 %0, {%1, %2};" : "=l"(b2[1]) : "f"(bf0.z), "f"(bf0.w));
            asm("mov.b64 %0, {%1, %2};" : "=l"(b2[2]) : "f"(bf1.x), "f"(bf1.y));
            asm("mov.b64 %0, {%1, %2};" : "=l"(b2[3]) : "f"(bf1.z), "f"(bf1.w));
#pragma unroll
            for (int r = 0; r < 8; ++r) {
                unsigned long long a2 = pack2(ar[r]);
#pragma unroll
                for (int j = 0; j < 4; ++j) fma2(acc[r][j], a2, b2[j]);
            }
        }
        __syncthreads();
    }

#pragma unroll
    for (int r = 0; r < 8; ++r) {
        int row = bm + ty * 8 + r;
        float* crow;
        if (REMAP) {
            int tt = row >> 5;  // t (B_=32)
            int bb = row & 31;  // b
            crow = C + (size_t)(bb * TDEC + tt) * N;
        } else {
            crow = C + (size_t)row * N;
        }
        int n0 = bn + tx * 8;
        float o[8];
#pragma unroll
        for (int j = 0; j < 4; ++j) {
            float lo, hi;
            unpack2(acc[r][j], lo, hi);
            o[2 * j] = lo;
            o[2 * j + 1] = hi;
        }
#pragma unroll
        for (int j = 0; j < 8; ++j) o[j] += bias[n0 + j];
        *reinterpret_cast<float4*>(crow + n0) = make_float4(o[0], o[1], o[2], o[3]);
        *reinterpret_cast<float4*>(crow + n0 + 4) = make_float4(o[4], o[5], o[6], o[7]);
    }
}

// ---------------- launch ----------------
extern "C" void kernel_launch(void* const* d_in, const int* in_sizes, int n_in, void* d_out,
                              int out_size) {
    (void)in_sizes;
    (void)n_in;
    (void)out_size;
    const float* enc = (const float*)d_in[0];
    const int* dec = (const int*)d_in[1];
    const float* h0 = (const float*)d_in[2];
    const float* noise = (const float*)d_in[3];
    const float* emb = (const float*)d_in[4];
    const float* W_ih = (const float*)d_in[5];
    const float* b_ih = (const float*)d_in[6];
    const float* W_hh = (const float*)d_in[7];
    const float* b_hh = (const float*)d_in[8];
    const float* Wm = (const float*)d_in[9];
    const float* Vm = (const float*)d_in[10];
    const float* bm = (const float*)d_in[11];
    const float* vvm = (const float*)d_in[12];
    const float* gm = (const float*)d_in[13];
    const float* vbm = (const float*)d_in[14];
    const float* rm = (const float*)d_in[15];
    const float* Wc = (const float*)d_in[16];
    const float* Vc = (const float*)d_in[17];
    const float* bc = (const float*)d_in[18];
    const float* vvc = (const float*)d_in[19];
    const float* gc = (const float*)d_in[20];
    const float* vbc = (const float*)d_in[21];
    const float* rc = (const float*)d_in[22];
    const float* W_comb = (const float*)d_in[23];
    const float* W_proj = (const float*)d_in[24];
    const float* b_proj = (const float*)d_in[25];
    float* out = (float*)d_out;

    void *pEncWm = nullptr, *pEncWc = nullptr, *pAttn = nullptr;
    cudaGetSymbolAddress(&pEncWm, g_encWm);
    cudaGetSymbolAddress(&pEncWc, g_encWc);
    cudaGetSymbolAddress(&pAttn, g_attn);

    // one-time prep: transposed weights, weight-norm vectors, biases, flag reset
    k_init<<<65, 256>>>(W_ih, b_ih, W_hh, b_hh, Vm, Vc, W_comb, vvm, gm, vbm, rm, vvc, gc,
                        vbc, rc);
    // step-invariant encoder projections
    gemm_tn<false><<<dim3(2, 128), 256>>>(enc, Wm, bm, (float*)pEncWm, B_ * TENC, DIM, DIM);
    gemm_tn<false><<<dim3(2, 128), 256>>>(enc, Wc, bc, (float*)pEncWc, B_ * TENC, DIM, DIM);
    // all 32 decoder steps: decoupled per-batch pipelines, no grid barrier
    k_steps<<<128, 256>>>(enc, dec, h0, noise, emb);
    // deferred vocabulary projection
    gemm_tn<true><<<dim3(VOCAB_ / 128, (TDEC * B_) / 128), 256>>>(
        (const float*)pAttn, W_proj, b_proj, out, TDEC * B_, VOCAB_, DIM);
}

// round 10
// speedup vs baseline: 1.1524x; 1.1524x over previous
#include <cuda_runtime.h>
#include <cuda_bf16.h>
#include <cstdint>

#define B_     32
#define TENC   512
#define TDEC   32
#define DIM    256
#define VOCAB_ 32000
#define SOS_   1

// ---------------- device scratch ----------------
__device__ float g_encWm[B_ * TENC * DIM];   // enc@Wm.T + bm
__device__ float g_encWc[B_ * TENC * DIM];   // enc@Wc.T + bc
__device__ float g_hVm[B_ * DIM];
__device__ float g_hVc[B_ * DIM];
__device__ float g_p[B_ * TENC];
__device__ float g_ecb[B_ * TENC];
__device__ float g_attn[TDEC * B_ * DIM];    // row = t*B + b
__device__ float g_h[B_ * DIM];              // current hidden state (published)
__device__ float g_uch[B_ * DIM];            // Wcomb_h @ h (published by worker q2)
__device__ float g_xw[B_ * (TDEC + 1) * DIM];// W_ih@emb[tok]+biasr, [b][t] t=0 is SOS
__device__ float g_WihT[256 * 256];          // [k][o]
__device__ float g_WhhT[256 * 256];          // [k][o]
__device__ float g_VmT[256 * 256];           // [k][o]
__device__ float g_VcT[256 * 256];           // [k][o]
__device__ float g_WcombT[512 * 256];        // [k][o], k<256 ctx-half, k>=256 h-half
__device__ float g_biasr[256];               // b_ih + b_hh
__device__ float g_wm[256];
__device__ float g_wc[256];
__device__ float g_cst[2];
__device__ unsigned g_flags[B_ * 32];        // per-batch 128B line: 0=hgen 1=hvm 2=hvc 3=uch 4=ecnt
#define FLG(b, i) (&g_flags[(b) * 32 + (i)])

// ---------------- helpers ----------------
__device__ __forceinline__ float warp_sum(float v) {
#pragma unroll
    for (int s = 16; s; s >>= 1) v += __shfl_xor_sync(0xffffffffu, v, s);
    return v;
}
__device__ __forceinline__ float tanh_fast(float x) {
    float e = __expf(2.0f * x);
    return 1.0f - __fdividef(2.0f, e + 1.0f);
}
__device__ __forceinline__ float sigmoid_fast(float x) {
    return __fdividef(1.0f, 1.0f + __expf(-x));
}

// exclusive prefix over 256 per-thread pair-sums
__device__ __forceinline__ float pair_excl(float ps, float* s_w8) {
    int tid = threadIdx.x, lane = tid & 31, wid = tid >> 5;
    float s = ps;
#pragma unroll
    for (int d = 1; d < 32; d <<= 1) {
        float n = __shfl_up_sync(0xffffffffu, s, d);
        if (lane >= d) s += n;
    }
    __syncthreads();
    if (lane == 31) s_w8[wid] = s;
    __syncthreads();
    if (tid < 32) {
        float v = (lane < 8) ? s_w8[lane] : 0.0f;
#pragma unroll
        for (int d = 1; d < 8; d <<= 1) {
            float n = __shfl_up_sync(0xffffffffu, v, d);
            if (lane >= d) v += n;
        }
        if (lane < 8) s_w8[lane] = v;
    }
    __syncthreads();
    float woff = wid ? s_w8[wid - 1] : 0.0f;
    return woff + (s - ps);
}

__device__ __forceinline__ float max512(float m, float* s_w8) {
    int tid = threadIdx.x, lane = tid & 31, wid = tid >> 5;
#pragma unroll
    for (int s = 16; s; s >>= 1) m = fmaxf(m, __shfl_xor_sync(0xffffffffu, m, s));
    __syncthreads();
    if (lane == 0) s_w8[wid] = m;
    __syncthreads();
    if (tid < 32) {
        float v = (lane < 8) ? s_w8[lane] : -1e30f;
#pragma unroll
        for (int s = 4; s; s >>= 1) v = fmaxf(v, __shfl_xor_sync(0xffffffffu, v, s));
        if (lane == 0) s_w8[0] = v;
    }
    __syncthreads();
    return s_w8[0];
}

// y[o=tid] = sum_{k<256} x[k] * WT[k*256+o]   (LD.128 coalesced, k-split 4)
__device__ __forceinline__ float gemv256(const float* __restrict__ WT,
                                         const float* __restrict__ x, float* s_part) {
    int tid = threadIdx.x;
    int j = tid & 63, kq = tid >> 6;
    __syncthreads();
    const float4* Wp = reinterpret_cast<const float4*>(WT);
    float4 acc = make_float4(0.f, 0.f, 0.f, 0.f);
    int k0 = kq * 64;
#pragma unroll 8
    for (int k = k0; k < k0 + 64; ++k) {
        float f = x[k];
        float4 w = Wp[(size_t)k * 64 + j];
        acc.x = fmaf(f, w.x, acc.x);
        acc.y = fmaf(f, w.y, acc.y);
        acc.z = fmaf(f, w.z, acc.z);
        acc.w = fmaf(f, w.w, acc.w);
    }
    reinterpret_cast<float4*>(s_part)[kq * 64 + j] = acc;
    __syncthreads();
    return s_part[tid] + s_part[256 + tid] + s_part[512 + tid] + s_part[768 + tid];
}

// publish: per-thread stores done -> fence -> barrier -> one atomic
__device__ __forceinline__ void publish_exch(unsigned* flag, unsigned v) {
    __threadfence();
    __syncthreads();
    if (threadIdx.x == 0) atomicExch(flag, v);
}
__device__ __forceinline__ void publish_add(unsigned* flag) {
    __threadfence();
    __syncthreads();
    if (threadIdx.x == 0) atomicAdd(flag, 1u);
}
// CTA-wide wait: only thread 0 polls L2, then barrier
__device__ __forceinline__ void spin_cta(const unsigned* flag, unsigned v) {
    if (threadIdx.x == 0) {
        const volatile unsigned* f = (const volatile unsigned*)flag;
        while (*f < v) {}
    }
    __syncthreads();
}

// ---------------- init ----------------
__global__ void k_init(const float* __restrict__ W_ih, const float* __restrict__ b_ih,
                       const float* __restrict__ W_hh, const float* __restrict__ b_hh,
                       const float* __restrict__ Vm, const float* __restrict__ Vc,
                       const float* __restrict__ W_comb,
                       const float* __restrict__ vvm, const float* __restrict__ gm,
                       const float* __restrict__ vbm, const float* __restrict__ rm,
                       const float* __restrict__ vvc, const float* __restrict__ gc,
                       const float* __restrict__ vbc, const float* __restrict__ rc) {
    int bidx = blockIdx.x, tid = threadIdx.x;
    if (bidx < 96) {
        for (int idx = bidx * 256 + tid; idx < 393216; idx += 96 * 256) {
            if (idx < 65536) {
                int k = idx >> 8, o = idx & 255;
                g_WihT[idx] = W_ih[o * 256 + k];
            } else if (idx < 131072) {
                int r = idx - 65536;
                int k = r >> 8, o = r & 255;
                g_WhhT[r] = W_hh[o * 256 + k];
            } else if (idx < 196608) {
                int r = idx - 131072;
                int k = r >> 8, o = r & 255;
                g_VmT[r] = Vm[o * 256 + k];
            } else if (idx < 262144) {
                int r = idx - 196608;
                int k = r >> 8, o = r & 255;
                g_VcT[r] = Vc[o * 256 + k];
            } else {
                int r = idx - 262144;
                int k = r >> 8, o = r & 255;
                g_WcombT[r] = W_comb[o * 512 + k];
            }
        }
    } else {
        __shared__ float red[256];
        for (int i = tid; i < B_ * 32; i += 256) g_flags[i] = 0u;
        float v = vvm[tid];
        red[tid] = v * v;
        __syncthreads();
        for (int s = 128; s > 0; s >>= 1) {
            if (tid < s) red[tid] += red[tid + s];
            __syncthreads();
        }
        float nm = sqrtf(red[0]);
        __syncthreads();
        g_wm[tid] = vvm[tid] * gm[0] / nm;
        float v2 = vvc[tid];
        red[tid] = v2 * v2;
        __syncthreads();
        for (int s = 128; s > 0; s >>= 1) {
            if (tid < s) red[tid] += red[tid + s];
            __syncthreads();
        }
        float nc = sqrtf(red[0]);
        __syncthreads();
        g_wc[tid] = vvc[tid] * gc[0] / nc;
        g_biasr[tid] = b_ih[tid] + b_hh[tid];
        if (tid == 0) {
            g_cst[0] = vbm[0] + rm[0];
            g_cst[1] = vbc[0] + rc[0];
        }
    }
}

// ---------------- token projections: xw[b][t] = W_ih@emb[tok]+biasr ----------------
__global__ __launch_bounds__(256) void k_xw(const int* __restrict__ dec,
                                            const float* __restrict__ emb) {
    __shared__ float s_x[256];
    __shared__ float s_part[1024];
    int t = blockIdx.x, b = blockIdx.y, tid = threadIdx.x;
    int tok = (t == 0) ? SOS_ : dec[b * TDEC + (t - 1)];
    s_x[tid] = __ldg(&emb[(size_t)tok * DIM + tid]);
    float y = gemv256(g_WihT, s_x, s_part) + g_biasr[tid];
    g_xw[((size_t)b * (TDEC + 1) + t) * DIM + tid] = y;
}

// ---------------- energy for quarter q of batch b at step t ----------------
template <bool LOCAL>
__device__ __forceinline__ void energy_quarter(int b, int q, int t,
                                               const float* __restrict__ noise,
                                               const float* rhm, const float* rhc,
                                               const float* rwm, const float* rwc,
                                               float cm, float cc, float* s_p,
                                               float* s_ec) {
    int tid = threadIdx.x, wid = tid >> 5, lane = tid & 31;
    int tt0 = q * 128 + wid * 16;
    const size_t base = (size_t)b * TENC;
#pragma unroll 1
    for (int i2 = 0; i2 < 16; ++i2) {
        int tt = tt0 + i2;
        const float4* em4 =
            reinterpret_cast<const float4*>(g_encWm + (base + tt) * DIM) + lane * 2;
        const float4* ec4 =
            reinterpret_cast<const float4*>(g_encWc + (base + tt) * DIM) + lane * 2;
        float4 m0 = em4[0], m1 = em4[1];
        float4 c0 = ec4[0], c1 = ec4[1];
        float mv[8] = {m0.x, m0.y, m0.z, m0.w, m1.x, m1.y, m1.z, m1.w};
        float cv[8] = {c0.x, c0.y, c0.z, c0.w, c1.x, c1.y, c1.z, c1.w};
        float am = 0.f, ac = 0.f;
#pragma unroll
        for (int j = 0; j < 8; ++j) {
            am = fmaf(tanh_fast(mv[j] + rhm[j]), rwm[j], am);
            ac = fmaf(tanh_fast(cv[j] + rhc[j]), rwc[j], ac);
        }
        am = warp_sum(am);
        ac = warp_sum(ac);
        if (lane == 0) {
            float pp =
                sigmoid_fast(am + cm + __ldg(&noise[((size_t)t * B_ + b) * TENC + tt]));
            if (LOCAL) {
                s_p[tt] = pp;
                s_ec[tt] = ac + cc;
            } else {
                __stcg(&g_p[b * TENC + tt], pp);
                __stcg(&g_ecb[b * TENC + tt], ac + cc);
            }
        }
    }
}

// ---------------- persistent step kernel ----------------
// 128 CTAs: b = cta&31, q = cta>>5. q0 = post+energy, q1 = energy+hVc, q2 = energy+uch,
// q3 = energy only.
__global__ __launch_bounds__(256, 1) void k_steps(const float* __restrict__ enc,
                                                  const float* __restrict__ h0,
                                                  const float* __restrict__ noise) {
    __shared__ float s_alpha[512];
    __shared__ float s_h[256];
    __shared__ float s_p[512], s_ec[512];
    __shared__ float s_eu[512], s_ratio[512], s_beta[512];
    __shared__ float s_ctx[256];   // post: context; workers: h buffer
    __shared__ float s_part[1024];
    __shared__ float s_w8[32];

    int tid = threadIdx.x, cta = blockIdx.x;
    int b = cta & 31, q = cta >> 5;
    int lane = tid & 31;
    int a0 = lane * 8;

    float cm = g_cst[0], cc = g_cst[1];
    float rwm[8], rwc[8];
#pragma unroll
    for (int j = 0; j < 8; ++j) {
        rwm[j] = __ldg(&g_wm[a0 + j]);
        rwc[j] = __ldg(&g_wc[a0 + j]);
    }

    // ---- prologue: H_0 = tanh(xw_sos + Whh@h0); hV split post/q1 ----
    if (q == 0) {
        s_h[tid] = h0[b * DIM + tid];
        s_alpha[tid] = (tid == 0) ? 1.0f : 0.0f;
        s_alpha[256 + tid] = 0.0f;
        float yh = gemv256(g_WhhT, s_h, s_part);
        float hn = tanh_fast(yh + __ldg(&g_xw[((size_t)b * (TDEC + 1)) * DIM + tid]));
        __syncthreads();
        s_h[tid] = hn;
        __stcg(&g_h[b * DIM + tid], hn);
        publish_exch(FLG(b, 0), 1u);
        float ym = gemv256(g_VmT, s_h, s_part);
        __stcg(&g_hVm[b * DIM + tid], ym);
        publish_exch(FLG(b, 1), 1u);
    } else if (q == 1) {
        spin_cta(FLG(b, 0), 1u);
        s_ctx[tid] = __ldcg(&g_h[b * DIM + tid]);
        float yc = gemv256(g_VcT, s_ctx, s_part);
        __stcg(&g_hVc[b * DIM + tid], yc);
        publish_exch(FLG(b, 2), 1u);
    }

#pragma unroll 1
    for (int t = 0; t < TDEC; ++t) {
        // wait both hV halves for this step
        spin_cta(FLG(b, 1), (unsigned)(t + 1));
        spin_cta(FLG(b, 2), (unsigned)(t + 1));
        float rhm[8], rhc[8];
        {
            float4 v0 = __ldcg(reinterpret_cast<const float4*>(g_hVm + b * DIM + a0));
            float4 v1 = __ldcg(reinterpret_cast<const float4*>(g_hVm + b * DIM + a0 + 4));
            rhm[0] = v0.x; rhm[1] = v0.y; rhm[2] = v0.z; rhm[3] = v0.w;
            rhm[4] = v1.x; rhm[5] = v1.y; rhm[6] = v1.z; rhm[7] = v1.w;
            float4 w0 = __ldcg(reinterpret_cast<const float4*>(g_hVc + b * DIM + a0));
            float4 w1 = __ldcg(reinterpret_cast<const float4*>(g_hVc + b * DIM + a0 + 4));
            rhc[0] = w0.x; rhc[1] = w0.y; rhc[2] = w0.z; rhc[3] = w0.w;
            rhc[4] = w1.x; rhc[5] = w1.y; rhc[6] = w1.z; rhc[7] = w1.w;
        }

        if (q == 0) {
            energy_quarter<true>(b, 0, t, noise, rhm, rhc, rwm, rwc, cm, cc, s_p, s_ec);
            __syncthreads();
        } else {
            energy_quarter<false>(b, q, t, noise, rhm, rhc, rwm, rwc, cm, cc, nullptr,
                                  nullptr);
            publish_add(FLG(b, 4));
            if (q == 2) {
                // uch = Wcomb_h @ H_t  (g_h still holds H_t: post updates it only
                // after consuming uch)
                s_ctx[tid] = __ldcg(&g_h[b * DIM + tid]);
                float u = gemv256(g_WcombT + 256 * 256, s_ctx, s_part);
                __stcg(&g_uch[b * DIM + tid], u);
                publish_exch(FLG(b, 3), (unsigned)(t + 1));
            } else if (q == 1 && t < TDEC - 1) {
                spin_cta(FLG(b, 0), (unsigned)(t + 2));
                s_ctx[tid] = __ldcg(&g_h[b * DIM + tid]);
                float yc = gemv256(g_VcT, s_ctx, s_part);
                __stcg(&g_hVc[b * DIM + tid], yc);
                publish_exch(FLG(b, 2), (unsigned)(t + 2));
            }
            continue;
        }

        // ---- post phase (q == 0) ----
        spin_cta(FLG(b, 4), 3u * (unsigned)(t + 1));

        int j0 = 2 * tid, j1 = 2 * tid + 1;
        float p0 = (tid < 64) ? s_p[j0] : __ldcg(&g_p[b * TENC + j0]);
        float p1 = (tid < 64) ? s_p[j1] : __ldcg(&g_p[b * TENC + j1]);
        float l0 = __logf(fminf(fmaxf(1.0f - p0, 1e-10f), 1.0f));
        float l1 = __logf(fminf(fmaxf(1.0f - p1, 1e-10f), 1.0f));
        float eP = pair_excl(l0 + l1, s_w8);
        float cp0 = __expf(eP);
        float cp1 = __expf(eP + l0);
        float A0 = s_alpha[j0], A1 = s_alpha[j1];
        float r0 = __fdividef(A0, fmaxf(cp0, 1e-10f));
        float r1 = __fdividef(A1, fmaxf(cp1, 1e-10f));
        float eS = pair_excl(r0 + r1, s_w8);
        float na0 = p0 * cp0 * (eS + r0);
        float na1 = p1 * cp1 * (eS + r0 + r1);
        s_alpha[j0] = na0;
        s_alpha[j1] = na1;

        float e0 = (tid < 64) ? s_ec[j0] : __ldcg(&g_ecb[b * TENC + j0]);
        float e1 = (tid < 64) ? s_ec[j1] : __ldcg(&g_ecb[b * TENC + j1]);
        float mx = max512(fmaxf(e0, e1), s_w8);
        float eu0 = __expf(e0 - mx), eu1 = __expf(e1 - mx);
        s_eu[j0] = eu0;
        s_eu[j1] = eu1;
        __syncthreads();
        float d0 = 0.0f, d1 = 0.0f;
#pragma unroll
        for (int k = 0; k < 8; ++k) {
            int q0i = j0 - k, q1i = j1 - k;
            if (q0i >= 0) d0 += s_eu[q0i];
            if (q1i >= 0) d1 += s_eu[q1i];
        }
        s_ratio[j0] = __fdividef(na0, fmaxf(d0, 1e-10f));
        s_ratio[j1] = __fdividef(na1, fmaxf(d1, 1e-10f));
        __syncthreads();
        float b0 = 0.0f, b1 = 0.0f;
#pragma unroll
        for (int k = 0; k < 8; ++k) {
            int q0i = j0 + k, q1i = j1 + k;
            if (q0i < TENC) b0 += s_ratio[q0i];
            if (q1i < TENC) b1 += s_ratio[q1i];
        }
        s_beta[j0] = eu0 * b0;
        s_beta[j1] = eu1 * b1;
        __syncthreads();

        // context = beta @ enc[b]
        {
            int jj = tid & 63, tq4 = tid >> 6;
            const float4* ep = reinterpret_cast<const float4*>(enc) +
                               (size_t)(b * TENC + tq4 * 128) * (DIM / 4) + jj;
            float4 acc = make_float4(0.f, 0.f, 0.f, 0.f);
#pragma unroll 4
            for (int ttt = 0; ttt < 128; ++ttt) {
                float f = s_beta[tq4 * 128 + ttt];
                float4 e4 = ep[(size_t)ttt * 64];
                acc.x = fmaf(f, e4.x, acc.x);
                acc.y = fmaf(f, e4.y, acc.y);
                acc.z = fmaf(f, e4.z, acc.z);
                acc.w = fmaf(f, e4.w, acc.w);
            }
            reinterpret_cast<float4*>(s_part)[tq4 * 64 + jj] = acc;
        }
        __syncthreads();
        s_ctx[tid] = s_part[tid] + s_part[256 + tid] + s_part[512 + tid] + s_part[768 + tid];

        // attn = tanh(Wcomb_ctx@ctx + uch)
        float av = gemv256(g_WcombT, s_ctx, s_part);
        spin_cta(FLG(b, 3), (unsigned)(t + 1));
        float at = tanh_fast(av + __ldcg(&g_uch[b * DIM + tid]));
        __stcg(&g_attn[((size_t)t * B_ + b) * DIM + tid], at);

        if (t < TDEC - 1) {
            // H_{t+1} = tanh(xw[b][t+1] + Whh@H_t)
            float yh = gemv256(g_WhhT, s_h, s_part);
            float hn = tanh_fast(
                yh + __ldg(&g_xw[((size_t)b * (TDEC + 1) + t + 1) * DIM + tid]));
            __syncthreads();
            s_h[tid] = hn;
            __stcg(&g_h[b * DIM + tid], hn);
            publish_exch(FLG(b, 0), (unsigned)(t + 2));
            float ym = gemv256(g_VmT, s_h, s_part);
            __stcg(&g_hVm[b * DIM + tid], ym);
            publish_exch(FLG(b, 1), (unsigned)(t + 2));
        }
    }
}

// ---------------- GEMM v2: k-pair FFMA2, conflict-free, occ 1 ----------------
__device__ __forceinline__ unsigned long long pk2(float lo, float hi) {
    unsigned long long r;
    asm("mov.b64 %0, {%1, %2};" : "=l"(r) : "f"(lo), "f"(hi));
    return r;
}
__device__ __forceinline__ void fma2(unsigned long long& acc, unsigned long long a,
                                     unsigned long long b) {
    asm("fma.rn.f32x2 %0, %1, %2, %0;" : "+l"(acc) : "l"(a), "l"(b));
}
__device__ __forceinline__ void unpack2(unsigned long long v, float& lo, float& hi) {
    asm("mov.b64 {%0, %1}, %2;" : "=f"(lo), "=f"(hi) : "l"(v));
}

// C[M,N] = A[M,K] @ B[N,K]^T + bias; 128x128 tile, BK=16, 256 thr, 8x8/thread
// (interleave 16). REMAP: out row (t*B+b) -> (b*TDEC+t).
template <bool REMAP>
__global__ __launch_bounds__(256, 1) void gemm2(const float* __restrict__ A,
                                                const float* __restrict__ Bw,
                                                const float* __restrict__ bias,
                                                float* __restrict__ C, int M, int N,
                                                int K) {
    __shared__ unsigned long long Ap[8][130];
    __shared__ unsigned long long Bp[8][130];
    int tid = threadIdx.x, tx = tid & 15, ty = tid >> 4;
    int bm = blockIdx.y * 128, bn = blockIdx.x * 128;
    int lrow = tid >> 1, lk = (tid & 1) * 8, kb = (tid & 1) * 4;
    const float* Aptr = A + (size_t)(bm + lrow) * K + lk;
    const float* Bptr = Bw + (size_t)(bn + lrow) * K + lk;

    unsigned long long acc[8][8];
#pragma unroll
    for (int r = 0; r < 8; ++r)
#pragma unroll
        for (int c = 0; c < 8; ++c) acc[r][c] = 0ull;

    float4 fa0 = *(const float4*)(Aptr), fa1 = *(const float4*)(Aptr + 4);
    float4 fb0 = *(const float4*)(Bptr), fb1 = *(const float4*)(Bptr + 4);

    for (int k0 = 0; k0 < K; k0 += 16) {
        Ap[kb + 0][lrow] = pk2(fa0.x, fa0.y);
        Ap[kb + 1][lrow] = pk2(fa0.z, fa0.w);
        Ap[kb + 2][lrow] = pk2(fa1.x, fa1.y);
        Ap[kb + 3][lrow] = pk2(fa1.z, fa1.w);
        Bp[kb + 0][lrow] = pk2(fb0.x, fb0.y);
        Bp[kb + 1][lrow] = pk2(fb0.z, fb0.w);
        Bp[kb + 2][lrow] = pk2(fb1.x, fb1.y);
        Bp[kb + 3][lrow] = pk2(fb1.z, fb1.w);
        __syncthreads();
        if (k0 + 16 < K) {
            fa0 = *(const float4*)(Aptr + k0 + 16);
            fa1 = *(const float4*)(Aptr + k0 + 20);
            fb0 = *(const float4*)(Bptr + k0 + 16);
            fb1 = *(const float4*)(Bptr + k0 + 20);
        }
#pragma unroll
        for (int k2 = 0; k2 < 8; ++k2) {
            unsigned long long av[8], bv[8];
#pragma unroll
            for (int r = 0; r < 8; ++r) av[r] = Ap[k2][ty + 16 * r];
#pragma unroll
            for (int c = 0; c < 8; ++c) bv[c] = Bp[k2][tx + 16 * c];
#pragma unroll
            for (int r = 0; r < 8; ++r)
#pragma unroll
                for (int c = 0; c < 8; ++c) fma2(acc[r][c], av[r], bv[c]);
        }
        __syncthreads();
    }

    float bb[8];
#pragma unroll
    for (int c = 0; c < 8; ++c) bb[c] = bias[bn + tx + 16 * c];
#pragma unroll
    for (int r = 0; r < 8; ++r) {
        int row = bm + ty + 16 * r;
        float* crow;
        if (REMAP) {
            crow = C + (size_t)((row & 31) * TDEC + (row >> 5)) * N;
        } else {
            crow = C + (size_t)row * N;
        }
#pragma unroll
        for (int c = 0; c < 8; ++c) {
            float lo, hi;
            unpack2(acc[r][c], lo, hi);
            crow[bn + tx + 16 * c] = lo + hi + bb[c];
        }
    }
}

// ---------------- launch ----------------
extern "C" void kernel_launch(void* const* d_in, const int* in_sizes, int n_in, void* d_out,
                              int out_size) {
    (void)in_sizes;
    (void)n_in;
    (void)out_size;
    const float* enc = (const float*)d_in[0];
    const int* dec = (const int*)d_in[1];
    const float* h0 = (const float*)d_in[2];
    const float* noise = (const float*)d_in[3];
    const float* emb = (const float*)d_in[4];
    const float* W_ih = (const float*)d_in[5];
    const float* b_ih = (const float*)d_in[6];
    const float* W_hh = (const float*)d_in[7];
    const float* b_hh = (const float*)d_in[8];
    const float* Wm = (const float*)d_in[9];
    const float* Vm = (const float*)d_in[10];
    const float* bm = (const float*)d_in[11];
    const float* vvm = (const float*)d_in[12];
    const float* gm = (const float*)d_in[13];
    const float* vbm = (const float*)d_in[14];
    const float* rm = (const float*)d_in[15];
    const float* Wc = (const float*)d_in[16];
    const float* Vc = (const float*)d_in[17];
    const float* bc = (const float*)d_in[18];
    const float* vvc = (const float*)d_in[19];
    const float* gc = (const float*)d_in[20];
    const float* vbc = (const float*)d_in[21];
    const float* rc = (const float*)d_in[22];
    const float* W_comb = (const float*)d_in[23];
    const float* W_proj = (const float*)d_in[24];
    const float* b_proj = (const float*)d_in[25];
    float* out = (float*)d_out;

    void *pEncWm = nullptr, *pEncWc = nullptr, *pAttn = nullptr;
    cudaGetSymbolAddress(&pEncWm, g_encWm);
    cudaGetSymbolAddress(&pEncWc, g_encWc);
    cudaGetSymbolAddress(&pAttn, g_attn);

    // prep: transposes, weight-norm, biases, flags
    k_init<<<97, 256>>>(W_ih, b_ih, W_hh, b_hh, Vm, Vc, W_comb, vvm, gm, vbm, rm, vvc, gc,
                        vbc, rc);
    // token projections (static tokens -> off the chain)
    k_xw<<<dim3(TDEC + 1, B_), 256>>>(dec, emb);
    // step-invariant encoder projections
    gemm2<false><<<dim3(2, 128), 256>>>(enc, Wm, bm, (float*)pEncWm, B_ * TENC, DIM, DIM);
    gemm2<false><<<dim3(2, 128), 256>>>(enc, Wc, bc, (float*)pEncWc, B_ * TENC, DIM, DIM);
    // 32 decoder steps: per-batch pipelines with role-specialized CTAs
    k_steps<<<128, 256>>>(enc, h0, noise);
    // deferred vocabulary projection
    gemm2<true><<<dim3(VOCAB_ / 128, (TDEC * B_) / 128), 256>>>(
        (const float*)pAttn, W_proj, b_proj, out, TDEC * B_, VOCAB_, DIM);
}

// round 12
// speedup vs baseline: 1.3480x; 1.1697x over previous
#include <cuda_runtime.h>
#include <cuda_bf16.h>
#include <cstdint>

#define B_     32
#define TENC   512
#define TDEC   32
#define DIM    256
#define VOCAB_ 32000
#define SOS_   1
#define NTILE  ((TDEC * B_ / 128) * (VOCAB_ / 128))   // 8 * 250 = 2000

// ---------------- device scratch (parity double-buffered per-step data) ----------------
__device__ float g_encW[B_ * TENC * 512];    // cols 0-255 = enc@Wm.T+bm, 256-511 = enc@Wc.T+bc
__device__ float g_hVm[2][B_ * DIM];
__device__ float g_hVc[2][B_ * DIM];
__device__ float g_p[2][B_ * TENC];
__device__ float g_ecb[2][B_ * TENC];
__device__ float g_uch[2][B_ * DIM];
__device__ float g_h[2][B_ * DIM];           // H_t in g_h[t&1]
__device__ float g_attn[TDEC * B_ * DIM];    // row = t*B + b
__device__ float g_xw[B_ * (TDEC + 1) * DIM];
__device__ float g_WihT[256 * 256];
__device__ float g_WhhT[256 * 256];
__device__ float g_VmT[256 * 256];
__device__ float g_VcT[256 * 256];
__device__ float g_WcombT[512 * 256];        // k<256 ctx-half, k>=256 h-half
__device__ float g_Wmc[512 * 256];
__device__ float g_bmc[512];
__device__ float g_biasr[256];
__device__ float g_wm[256];
__device__ float g_wc[256];
__device__ float g_cst[2];
// flags per batch (128B line): 0=hgen 1=hvm 2=hvc 3=uch 4/5/6=energy step of worker q1/q2/q3
__device__ unsigned g_flags[B_ * 32];
__device__ unsigned g_scnt[TDEC];            // posts finished step t (0..32)
__device__ unsigned g_tile;
#define FLG(b, i) (&g_flags[(b) * 32 + (i)])

// ---------------- shared memory union ----------------
struct SmSt {
    float alpha[512];
    float h[256];
    float p[512], ec[512];
    float eu[512], ratio[512], beta[512];
    float ctx[256];
    float part[1024];
    float w8[32];
};
struct __align__(16) SmGm {
    unsigned long long Ap[128][10];
    unsigned long long Bp[128][10];
};
union SmU {
    SmSt st;
    SmGm gm;
};

// ---------------- helpers ----------------
__device__ __forceinline__ float warp_sum(float v) {
#pragma unroll
    for (int s = 16; s; s >>= 1) v += __shfl_xor_sync(0xffffffffu, v, s);
    return v;
}
__device__ __forceinline__ float tanh_fast(float x) {
    float e = __expf(2.0f * x);
    return 1.0f - __fdividef(2.0f, e + 1.0f);
}
__device__ __forceinline__ float sigmoid_fast(float x) {
    return __fdividef(1.0f, 1.0f + __expf(-x));
}
__device__ __forceinline__ unsigned long long pk2(float lo, float hi) {
    unsigned long long r;
    asm("mov.b64 %0, {%1, %2};" : "=l"(r) : "f"(lo), "f"(hi));
    return r;
}
__device__ __forceinline__ void fma2(unsigned long long& acc, unsigned long long a,
                                     unsigned long long b) {
    asm("fma.rn.f32x2 %0, %1, %2, %0;" : "+l"(acc) : "l"(a), "l"(b));
}
__device__ __forceinline__ void unpack2(unsigned long long v, float& lo, float& hi) {
    asm("mov.b64 {%0, %1}, %2;" : "=f"(lo), "=f"(hi) : "l"(v));
}

// exclusive prefix over 256 per-thread pair-sums
__device__ __forceinline__ float pair_excl(float ps, float* s_w8) {
    int tid = threadIdx.x, lane = tid & 31, wid = tid >> 5;
    float s = ps;
#pragma unroll
    for (int d = 1; d < 32; d <<= 1) {
        float n = __shfl_up_sync(0xffffffffu, s, d);
        if (lane >= d) s += n;
    }
    __syncthreads();
    if (lane == 31) s_w8[wid] = s;
    __syncthreads();
    if (tid < 32) {
        float v = (lane < 8) ? s_w8[lane] : 0.0f;
#pragma unroll
        for (int d = 1; d < 8; d <<= 1) {
            float n = __shfl_up_sync(0xffffffffu, v, d);
            if (lane >= d) v += n;
        }
        if (lane < 8) s_w8[lane] = v;
    }
    __syncthreads();
    float woff = wid ? s_w8[wid - 1] : 0.0f;
    return woff + (s - ps);
}

__device__ __forceinline__ float max512(float m, float* s_w8) {
    int tid = threadIdx.x, lane = tid & 31, wid = tid >> 5;
#pragma unroll
    for (int s = 16; s; s >>= 1) m = fmaxf(m, __shfl_xor_sync(0xffffffffu, m, s));
    __syncthreads();
    if (lane == 0) s_w8[wid] = m;
    __syncthreads();
    if (tid < 32) {
        float v = (lane < 8) ? s_w8[lane] : -1e30f;
#pragma unroll
        for (int s = 4; s; s >>= 1) v = fmaxf(v, __shfl_xor_sync(0xffffffffu, v, s));
        if (lane == 0) s_w8[0] = v;
    }
    __syncthreads();
    return s_w8[0];
}

// y[o=tid] = sum_{k<256} x[k] * WT[k*256+o]
__device__ __forceinline__ float gemv256(const float* __restrict__ WT,
                                         const float* __restrict__ x, float* s_part) {
    int tid = threadIdx.x;
    int j = tid & 63, kq = tid >> 6;
    __syncthreads();
    const float4* Wp = reinterpret_cast<const float4*>(WT);
    float4 acc = make_float4(0.f, 0.f, 0.f, 0.f);
    int k0 = kq * 64;
#pragma unroll 8
    for (int k = k0; k < k0 + 64; ++k) {
        float f = x[k];
        float4 w = Wp[(size_t)k * 64 + j];
        acc.x = fmaf(f, w.x, acc.x);
        acc.y = fmaf(f, w.y, acc.y);
        acc.z = fmaf(f, w.z, acc.z);
        acc.w = fmaf(f, w.w, acc.w);
    }
    reinterpret_cast<float4*>(s_part)[kq * 64 + j] = acc;
    __syncthreads();
    return s_part[tid] + s_part[256 + tid] + s_part[512 + tid] + s_part[768 + tid];
}

__device__ __forceinline__ void publish_exch(unsigned* flag, unsigned v) {
    __threadfence();
    __syncthreads();
    if (threadIdx.x == 0) atomicExch(flag, v);
}
__device__ __forceinline__ void spin_cta(const unsigned* flag, unsigned v) {
    if (threadIdx.x == 0) {
        const volatile unsigned* f = (const volatile unsigned*)flag;
        while (*f < v) {}
    }
    __syncthreads();
}

// ---------------- GEMM tile: C[128,128] = A[128xK] @ B[128xK]^T + bias, K=256 -------
template <bool REMAP, bool ACG>
__device__ void gemm_tile(const float* __restrict__ A, const float* __restrict__ Bw,
                          const float* __restrict__ bias, float* __restrict__ C, int bm,
                          int bn, int N, SmGm* sg) {
    const int K = 256;
    int tid = threadIdx.x, tx = tid & 15, ty = tid >> 4;
    int lrow = tid >> 1, lk = (tid & 1) * 8, kb = (tid & 1) * 4;
    const float* Aptr = A + (size_t)(bm + lrow) * K + lk;
    const float* Bptr = Bw + (size_t)(bn + lrow) * K + lk;

    unsigned long long acc[8][8];
#pragma unroll
    for (int r = 0; r < 8; ++r)
#pragma unroll
        for (int c = 0; c < 8; ++c) acc[r][c] = 0ull;

    float4 fa0, fa1, fb0, fb1;
    if (ACG) {
        fa0 = __ldcg((const float4*)Aptr);
        fa1 = __ldcg((const float4*)(Aptr + 4));
    } else {
        fa0 = *(const float4*)Aptr;
        fa1 = *(const float4*)(Aptr + 4);
    }
    fb0 = *(const float4*)Bptr;
    fb1 = *(const float4*)(Bptr + 4);

#pragma unroll 1
    for (int k0 = 0; k0 < K; k0 += 16) {
        sg->Ap[lrow][kb + 0] = pk2(fa0.x, fa0.y);
        sg->Ap[lrow][kb + 1] = pk2(fa0.z, fa0.w);
        sg->Ap[lrow][kb + 2] = pk2(fa1.x, fa1.y);
        sg->Ap[lrow][kb + 3] = pk2(fa1.z, fa1.w);
        sg->Bp[lrow][kb + 0] = pk2(fb0.x, fb0.y);
        sg->Bp[lrow][kb + 1] = pk2(fb0.z, fb0.w);
        sg->Bp[lrow][kb + 2] = pk2(fb1.x, fb1.y);
        sg->Bp[lrow][kb + 3] = pk2(fb1.z, fb1.w);
        __syncthreads();
        if (k0 + 16 < K) {
            if (ACG) {
                fa0 = __ldcg((const float4*)(Aptr + k0 + 16));
                fa1 = __ldcg((const float4*)(Aptr + k0 + 20));
            } else {
                fa0 = *(const float4*)(Aptr + k0 + 16);
                fa1 = *(const float4*)(Aptr + k0 + 20);
            }
            fb0 = *(const float4*)(Bptr + k0 + 16);
            fb1 = *(const float4*)(Bptr + k0 + 20);
        }
#pragma unroll
        for (int u = 0; u < 4; ++u) {
            ulonglong2 a2[8], b2[8];
#pragma unroll
            for (int r = 0; r < 8; ++r)
                a2[r] = *reinterpret_cast<const ulonglong2*>(&sg->Ap[ty + 16 * r][2 * u]);
#pragma unroll
            for (int c = 0; c < 8; ++c)
                b2[c] = *reinterpret_cast<const ulonglong2*>(&sg->Bp[tx + 16 * c][2 * u]);
#pragma unroll
            for (int r = 0; r < 8; ++r)
#pragma unroll
                for (int c = 0; c < 8; ++c) {
                    fma2(acc[r][c], a2[r].x, b2[c].x);
                    fma2(acc[r][c], a2[r].y, b2[c].y);
                }
        }
        __syncthreads();
    }

    float bb[8];
#pragma unroll
    for (int c = 0; c < 8; ++c) bb[c] = __ldg(&bias[bn + tx + 16 * c]);
#pragma unroll
    for (int r = 0; r < 8; ++r) {
        int row = bm + ty + 16 * r;
        float* crow;
        if (REMAP) {
            crow = C + (size_t)((row & 31) * TDEC + (row >> 5)) * N;
        } else {
            crow = C + (size_t)row * N;
        }
#pragma unroll
        for (int c = 0; c < 8; ++c) {
            float lo, hi;
            unpack2(acc[r][c], lo, hi);
            crow[bn + tx + 16 * c] = lo + hi + bb[c];
        }
    }
}

// ---------------- init ----------------
__global__ void k_init(const float* __restrict__ W_ih, const float* __restrict__ b_ih,
                       const float* __restrict__ W_hh, const float* __restrict__ b_hh,
                       const float* __restrict__ Vm, const float* __restrict__ Vc,
                       const float* __restrict__ W_comb, const float* __restrict__ Wm,
                       const float* __restrict__ Wc, const float* __restrict__ bm,
                       const float* __restrict__ bc, const float* __restrict__ vvm,
                       const float* __restrict__ gm, const float* __restrict__ vbm,
                       const float* __restrict__ rm, const float* __restrict__ vvc,
                       const float* __restrict__ gc, const float* __restrict__ vbc,
                       const float* __restrict__ rc) {
    int bidx = blockIdx.x, tid = threadIdx.x;
    if (bidx < 96) {
        for (int idx = bidx * 256 + tid; idx < 524288; idx += 96 * 256) {
            if (idx < 65536) {
                int k = idx >> 8, o = idx & 255;
                g_WihT[idx] = W_ih[o * 256 + k];
            } else if (idx < 131072) {
                int r = idx - 65536;
                int k = r >> 8, o = r & 255;
                g_WhhT[r] = W_hh[o * 256 + k];
            } else if (idx < 196608) {
                int r = idx - 131072;
                int k = r >> 8, o = r & 255;
                g_VmT[r] = Vm[o * 256 + k];
            } else if (idx < 262144) {
                int r = idx - 196608;
                int k = r >> 8, o = r & 255;
                g_VcT[r] = Vc[o * 256 + k];
            } else if (idx < 393216) {
                int r = idx - 262144;
                int k = r >> 8, o = r & 255;
                g_WcombT[r] = W_comb[o * 512 + k];
            } else {
                int r = idx - 393216;
                int o = r >> 8, k = r & 255;
                g_Wmc[r] = (o < 256) ? Wm[o * 256 + k] : Wc[(o - 256) * 256 + k];
            }
        }
    } else {
        __shared__ float red[256];
        for (int i = tid; i < B_ * 32; i += 256) g_flags[i] = 0u;
        if (tid < TDEC) g_scnt[tid] = 0u;
        if (tid == 0) g_tile = 0u;
        g_bmc[tid] = bm[tid];
        g_bmc[256 + tid] = bc[tid];
        float v = vvm[tid];
        red[tid] = v * v;
        __syncthreads();
        for (int s = 128; s > 0; s >>= 1) {
            if (tid < s) red[tid] += red[tid + s];
            __syncthreads();
        }
        float nm = sqrtf(red[0]);
        __syncthreads();
        g_wm[tid] = vvm[tid] * gm[0] / nm;
        float v2 = vvc[tid];
        red[tid] = v2 * v2;
        __syncthreads();
        for (int s = 128; s > 0; s >>= 1) {
            if (tid < s) red[tid] += red[tid + s];
            __syncthreads();
        }
        float nc = sqrtf(red[0]);
        __syncthreads();
        g_wc[tid] = vvc[tid] * gc[0] / nc;
        g_biasr[tid] = b_ih[tid] + b_hh[tid];
        if (tid == 0) {
            g_cst[0] = vbm[0] + rm[0];
            g_cst[1] = vbc[0] + rc[0];
        }
    }
}

// ---------------- token projections ----------------
__global__ __launch_bounds__(256) void k_xw(const int* __restrict__ dec,
                                            const float* __restrict__ emb) {
    __shared__ float s_x[256];
    __shared__ float s_part[1024];
    int t = blockIdx.x, b = blockIdx.y, tid = threadIdx.x;
    int tok = (t == 0) ? SOS_ : dec[b * TDEC + (t - 1)];
    s_x[tid] = __ldg(&emb[(size_t)tok * DIM + tid]);
    float y = gemv256(g_WihT, s_x, s_part) + g_biasr[tid];
    g_xw[((size_t)b * (TDEC + 1) + t) * DIM + tid] = y;
}

// ---------------- fused encoder projection: one GEMM, N=512 ----------------
__global__ __launch_bounds__(256, 1) void k_gemm_enc(const float* __restrict__ enc) {
    __shared__ SmGm sg;
    gemm_tile<false, false>(enc, g_Wmc, g_bmc, g_encW, blockIdx.y * 128, blockIdx.x * 128,
                            512, &sg);
}

// ---------------- energy for quarter q of batch b at step t ----------------
template <bool LOCAL>
__device__ __forceinline__ void energy_quarter(int b, int q, int t,
                                               const float* __restrict__ noise,
                                               const float* rhm, const float* rhc,
                                               const float* rwm, const float* rwc,
                                               float cm, float cc, float* out_p,
                                               float* out_ec) {
    int tid = threadIdx.x, wid = tid >> 5, lane = tid & 31;
    int tt0 = q * 128 + wid * 16;
    const size_t base = (size_t)b * TENC;
#pragma unroll 1
    for (int i2 = 0; i2 < 16; ++i2) {
        int tt = tt0 + i2;
        const float4* row4 = reinterpret_cast<const float4*>(g_encW + (base + tt) * 512);
        float4 m0 = row4[lane * 2], m1 = row4[lane * 2 + 1];
        float4 c0 = row4[64 + lane * 2], c1 = row4[64 + lane * 2 + 1];
        float mv[8] = {m0.x, m0.y, m0.z, m0.w, m1.x, m1.y, m1.z, m1.w};
        float cv[8] = {c0.x, c0.y, c0.z, c0.w, c1.x, c1.y, c1.z, c1.w};
        float am = 0.f, ac = 0.f;
#pragma unroll
        for (int j = 0; j < 8; ++j) {
            am = fmaf(tanh_fast(mv[j] + rhm[j]), rwm[j], am);
            ac = fmaf(tanh_fast(cv[j] + rhc[j]), rwc[j], ac);
        }
        am = warp_sum(am);
        ac = warp_sum(ac);
        if (lane == 0) {
            float pp =
                sigmoid_fast(am + cm + __ldg(&noise[((size_t)t * B_ + b) * TENC + tt]));
            if (LOCAL) {
                out_p[tt] = pp;
                out_ec[tt] = ac + cc;
            } else {
                __stcg(&out_p[tt], pp);
                __stcg(&out_ec[tt], ac + cc);
            }
        }
    }
}

// ---------------- persistent kernel: steps + work-steal vocab GEMM ----------------
// 148 CTAs. CTA<128: b=cta&31, q=cta>>5 (q0 post, q1 hVc, q2 uch, q3 hVm).
// CTA>=128: GEMM helpers. All CTAs drain the vocab tile queue at the end.
__global__ __launch_bounds__(256, 1) void k_steps(
    const float* __restrict__ enc, const float* __restrict__ h0,
    const float* __restrict__ noise, const float* __restrict__ Wproj,
    const float* __restrict__ bproj, float* __restrict__ out) {
    __shared__ SmU su;
    __shared__ int s_idx;

    int tid = threadIdx.x, cta = blockIdx.x;

    if (cta < 128) {
        int b = cta & 31, q = cta >> 5;
        int lane = tid & 31;
        int a0 = lane * 8;
        float cm = g_cst[0], cc = g_cst[1];
        float rwm[8], rwc[8];
#pragma unroll
        for (int j = 0; j < 8; ++j) {
            rwm[j] = __ldg(&g_wm[a0 + j]);
            rwc[j] = __ldg(&g_wc[a0 + j]);
        }

        // ---- prologue: H_0, hVm(0), hVc(0) -> parity 0 ----
        if (q == 0) {
            su.st.h[tid] = h0[b * DIM + tid];
            su.st.alpha[tid] = (tid == 0) ? 1.0f : 0.0f;
            su.st.alpha[256 + tid] = 0.0f;
            float yh = gemv256(g_WhhT, su.st.h, su.st.part);
            float hn = tanh_fast(yh + __ldg(&g_xw[((size_t)b * (TDEC + 1)) * DIM + tid]));
            __syncthreads();
            su.st.h[tid] = hn;
            __stcg(&g_h[0][b * DIM + tid], hn);
            publish_exch(FLG(b, 0), 1u);
        } else if (q == 1) {
            spin_cta(FLG(b, 0), 1u);
            su.st.ctx[tid] = __ldcg(&g_h[0][b * DIM + tid]);
            float yc = gemv256(g_VcT, su.st.ctx, su.st.part);
            __stcg(&g_hVc[0][b * DIM + tid], yc);
            publish_exch(FLG(b, 2), 1u);
        } else if (q == 3) {
            spin_cta(FLG(b, 0), 1u);
            su.st.ctx[tid] = __ldcg(&g_h[0][b * DIM + tid]);
            float ym = gemv256(g_VmT, su.st.ctx, su.st.part);
            __stcg(&g_hVm[0][b * DIM + tid], ym);
            publish_exch(FLG(b, 1), 1u);
        }

#pragma unroll 1
        for (int t = 0; t < TDEC; ++t) {
            int par = t & 1;
            // hV(t) available?
            spin_cta(FLG(b, 1), (unsigned)(t + 1));
            spin_cta(FLG(b, 2), (unsigned)(t + 1));
            float rhm[8], rhc[8];
            {
                const float* hm = g_hVm[par] + b * DIM + a0;
                const float* hc = g_hVc[par] + b * DIM + a0;
                float4 v0 = __ldcg(reinterpret_cast<const float4*>(hm));
                float4 v1 = __ldcg(reinterpret_cast<const float4*>(hm + 4));
                rhm[0] = v0.x; rhm[1] = v0.y; rhm[2] = v0.z; rhm[3] = v0.w;
                rhm[4] = v1.x; rhm[5] = v1.y; rhm[6] = v1.z; rhm[7] = v1.w;
                float4 w0 = __ldcg(reinterpret_cast<const float4*>(hc));
                float4 w1 = __ldcg(reinterpret_cast<const float4*>(hc + 4));
                rhc[0] = w0.x; rhc[1] = w0.y; rhc[2] = w0.z; rhc[3] = w0.w;
                rhc[4] = w1.x; rhc[5] = w1.y; rhc[6] = w1.z; rhc[7] = w1.w;
            }

            if (q == 0) {
                // 1) recurrence first: H_{t+1} published before the heavy work.
                //    Safe: q2 read g_h[par] before we consumed uch(t-1) last step.
                if (t < TDEC - 1) {
                    float yh = gemv256(g_WhhT, su.st.h, su.st.part);
                    float hn = tanh_fast(
                        yh + __ldg(&g_xw[((size_t)b * (TDEC + 1) + t + 1) * DIM + tid]));
                    __syncthreads();
                    su.st.h[tid] = hn;
                    __stcg(&g_h[1 - par][b * DIM + tid], hn);
                    publish_exch(FLG(b, 0), (unsigned)(t + 2));
                }
                // 2) own energy quarter (local smem)
                energy_quarter<true>(b, 0, t, noise, rhm, rhc, rwm, rwc, cm, cc, su.st.p,
                                     su.st.ec);
                __syncthreads();
                // 3) all three workers done with energy(t)?
                spin_cta(FLG(b, 4), (unsigned)(t + 1));
                spin_cta(FLG(b, 5), (unsigned)(t + 1));
                spin_cta(FLG(b, 6), (unsigned)(t + 1));

                // 4) alpha scans
                int j0 = 2 * tid, j1 = 2 * tid + 1;
                float p0 = (tid < 64) ? su.st.p[j0] : __ldcg(&g_p[par][b * TENC + j0]);
                float p1 = (tid < 64) ? su.st.p[j1] : __ldcg(&g_p[par][b * TENC + j1]);
                float l0 = __logf(fminf(fmaxf(1.0f - p0, 1e-10f), 1.0f));
                float l1 = __logf(fminf(fmaxf(1.0f - p1, 1e-10f), 1.0f));
                float eP = pair_excl(l0 + l1, su.st.w8);
                float cp0 = __expf(eP);
                float cp1 = __expf(eP + l0);
                float A0 = su.st.alpha[j0], A1 = su.st.alpha[j1];
                float r0 = __fdividef(A0, fmaxf(cp0, 1e-10f));
                float r1 = __fdividef(A1, fmaxf(cp1, 1e-10f));
                float eS = pair_excl(r0 + r1, su.st.w8);
                float na0 = p0 * cp0 * (eS + r0);
                float na1 = p1 * cp1 * (eS + r0 + r1);
                su.st.alpha[j0] = na0;
                su.st.alpha[j1] = na1;

                // 5) chunkwise beta
                float e0 = (tid < 64) ? su.st.ec[j0] : __ldcg(&g_ecb[par][b * TENC + j0]);
                float e1 = (tid < 64) ? su.st.ec[j1] : __ldcg(&g_ecb[par][b * TENC + j1]);
                float mx = max512(fmaxf(e0, e1), su.st.w8);
                float eu0 = __expf(e0 - mx), eu1 = __expf(e1 - mx);
                su.st.eu[j0] = eu0;
                su.st.eu[j1] = eu1;
                __syncthreads();
                float d0 = 0.0f, d1 = 0.0f;
#pragma unroll
                for (int k = 0; k < 8; ++k) {
                    int q0i = j0 - k, q1i = j1 - k;
                    if (q0i >= 0) d0 += su.st.eu[q0i];
                    if (q1i >= 0) d1 += su.st.eu[q1i];
                }
                su.st.ratio[j0] = __fdividef(na0, fmaxf(d0, 1e-10f));
                su.st.ratio[j1] = __fdividef(na1, fmaxf(d1, 1e-10f));
                __syncthreads();
                float b0 = 0.0f, b1 = 0.0f;
#pragma unroll
                for (int k = 0; k < 8; ++k) {
                    int q0i = j0 + k, q1i = j1 + k;
                    if (q0i < TENC) b0 += su.st.ratio[q0i];
                    if (q1i < TENC) b1 += su.st.ratio[q1i];
                }
                su.st.beta[j0] = eu0 * b0;
                su.st.beta[j1] = eu1 * b1;
                __syncthreads();

                // 6) context = beta @ enc[b]
                {
                    int jj = tid & 63, tq4 = tid >> 6;
                    const float4* ep = reinterpret_cast<const float4*>(enc) +
                                       (size_t)(b * TENC + tq4 * 128) * (DIM / 4) + jj;
                    float4 acc = make_float4(0.f, 0.f, 0.f, 0.f);
#pragma unroll 4
                    for (int ttt = 0; ttt < 128; ++ttt) {
                        float f = su.st.beta[tq4 * 128 + ttt];
                        float4 e4 = ep[(size_t)ttt * 64];
                        acc.x = fmaf(f, e4.x, acc.x);
                        acc.y = fmaf(f, e4.y, acc.y);
                        acc.z = fmaf(f, e4.z, acc.z);
                        acc.w = fmaf(f, e4.w, acc.w);
                    }
                    reinterpret_cast<float4*>(su.st.part)[tq4 * 64 + jj] = acc;
                }
                __syncthreads();
                su.st.ctx[tid] = su.st.part[tid] + su.st.part[256 + tid] +
                                 su.st.part[512 + tid] + su.st.part[768 + tid];

                // 7) attn = tanh(Wcomb_ctx@ctx + uch(t))
                float av = gemv256(g_WcombT, su.st.ctx, su.st.part);
                spin_cta(FLG(b, 3), (unsigned)(t + 1));
                float at = tanh_fast(av + __ldcg(&g_uch[par][b * DIM + tid]));
                __stcg(&g_attn[((size_t)t * B_ + b) * DIM + tid], at);
                __threadfence();
                __syncthreads();
                if (tid == 0) atomicAdd(&g_scnt[t], 1u);
            } else {
                energy_quarter<false>(b, q, t, noise, rhm, rhc, rwm, rwc, cm, cc,
                                      g_p[par] + b * TENC, g_ecb[par] + b * TENC);
                publish_exch(FLG(b, 3 + q), (unsigned)(t + 1));
                if (q == 2) {
                    // uch(t) = Wcomb_h @ H_t (parity slot t&1)
                    su.st.ctx[tid] = __ldcg(&g_h[par][b * DIM + tid]);
                    float u = gemv256(g_WcombT + 256 * 256, su.st.ctx, su.st.part);
                    __stcg(&g_uch[par][b * DIM + tid], u);
                    publish_exch(FLG(b, 3), (unsigned)(t + 1));
                } else if (q == 1 && t < TDEC - 1) {
                    spin_cta(FLG(b, 0), (unsigned)(t + 2));
                    su.st.ctx[tid] = __ldcg(&g_h[1 - par][b * DIM + tid]);
                    float yc = gemv256(g_VcT, su.st.ctx, su.st.part);
                    __stcg(&g_hVc[1 - par][b * DIM + tid], yc);
                    publish_exch(FLG(b, 2), (unsigned)(t + 2));
                } else if (q == 3 && t < TDEC - 1) {
                    spin_cta(FLG(b, 0), (unsigned)(t + 2));
                    su.st.ctx[tid] = __ldcg(&g_h[1 - par][b * DIM + tid]);
                    float ym = gemv256(g_VmT, su.st.ctx, su.st.part);
                    __stcg(&g_hVm[1 - par][b * DIM + tid], ym);
                    publish_exch(FLG(b, 1), (unsigned)(t + 2));
                }
            }
        }
    }

    // ---- work-steal vocab GEMM: tiles gated on step completion ----
    for (;;) {
        __syncthreads();
        if (tid == 0) s_idx = (int)atomicAdd(&g_tile, 1u);
        __syncthreads();
        int idx = s_idx;
        if (idx >= NTILE) break;
        int m = idx / (VOCAB_ / 128);
        int n = idx - m * (VOCAB_ / 128);
        if (tid == 0) {
            const volatile unsigned* f = &g_scnt[4 * m + 3];
            while (*f < 32u) __nanosleep(256);
        }
        __syncthreads();
        __threadfence();
        gemm_tile<true, true>(g_attn, Wproj, bproj, out, m * 128, n * 128, VOCAB_,
                              &su.gm);
    }
}

// ---------------- launch ----------------
extern "C" void kernel_launch(void* const* d_in, const int* in_sizes, int n_in, void* d_out,
                              int out_size) {
    (void)in_sizes;
    (void)n_in;
    (void)out_size;
    const float* enc = (const float*)d_in[0];
    const int* dec = (const int*)d_in[1];
    const float* h0 = (const float*)d_in[2];
    const float* noise = (const float*)d_in[3];
    const float* emb = (const float*)d_in[4];
    const float* W_ih = (const float*)d_in[5];
    const float* b_ih = (const float*)d_in[6];
    const float* W_hh = (const float*)d_in[7];
    const float* b_hh = (const float*)d_in[8];
    const float* Wm = (const float*)d_in[9];
    const float* Vm = (const float*)d_in[10];
    const float* bm = (const float*)d_in[11];
    const float* vvm = (const float*)d_in[12];
    const float* gm = (const float*)d_in[13];
    const float* vbm = (const float*)d_in[14];
    const float* rm = (const float*)d_in[15];
    const float* Wc = (const float*)d_in[16];
    const float* Vc = (const float*)d_in[17];
    const float* bc = (const float*)d_in[18];
    const float* vvc = (const float*)d_in[19];
    const float* gc = (const float*)d_in[20];
    const float* vbc = (const float*)d_in[21];
    const float* rc = (const float*)d_in[22];
    const float* W_comb = (const float*)d_in[23];
    const float* W_proj = (const float*)d_in[24];
    const float* b_proj = (const float*)d_in[25];
    float* out = (float*)d_out;

    k_init<<<97, 256>>>(W_ih, b_ih, W_hh, b_hh, Vm, Vc, W_comb, Wm, Wc, bm, bc, vvm, gm,
                        vbm, rm, vvc, gc, vbc, rc);
    k_xw<<<dim3(TDEC + 1, B_), 256>>>(dec, emb);
    k_gemm_enc<<<dim3(512 / 128, (B_ * TENC) / 128), 256>>>(enc);
    k_steps<<<148, 256>>>(enc, h0, noise, W_proj, b_proj, out);
}

// round 13
// speedup vs baseline: 1.4834x; 1.1005x over previous
#include <cuda_runtime.h>
#include <cuda_bf16.h>
#include <cstdint>

#define B_     32
#define TENC   512
#define TDEC   32
#define DIM    256
#define VOCAB_ 32000
#define SOS_   1
#define NTILE  ((TDEC * B_ / 128) * (VOCAB_ / 128))   // 2000

// ---------------- device scratch (parity double-buffered per-step data) ----------------
__device__ float g_encW[B_ * TENC * 512];    // cols 0-255 = enc@Wm.T+bm, 256-511 = enc@Wc.T+bc
__device__ float g_hVm[2][B_ * DIM];
__device__ float g_hVc[2][B_ * DIM];
__device__ float g_p[2][B_ * TENC];
__device__ float g_ecb[2][B_ * TENC];
__device__ float g_uch[2][B_ * DIM];
__device__ float g_h[2][B_ * DIM];           // H_t in g_h[t&1]
__device__ float g_attn[TDEC * B_ * DIM];    // row = t*B + b
__device__ float g_xw[B_ * (TDEC + 1) * DIM];
__device__ float g_WihT[256 * 256];
__device__ float g_WhhT[256 * 256];
__device__ float g_VmT[256 * 256];
__device__ float g_VcT[256 * 256];
__device__ float g_WcombT[512 * 256];        // k<256 ctx-half, k>=256 h-half
__device__ float g_Wmc[512 * 256];
__device__ float g_bmc[512];
__device__ float g_biasr[256];
__device__ float g_wm[256];
__device__ float g_wc[256];
__device__ float g_cst[2];
// flags per batch (128B line): 0=hgen 1=hvm 2=hvc 3=uch 4/5/6=energy step of worker q1/q2/q3
__device__ unsigned g_flags[B_ * 32];
__device__ unsigned g_scnt[TDEC];            // posts finished step t (0..32)
__device__ unsigned g_tile;
#define FLG(b, i) (&g_flags[(b) * 32 + (i)])

// ---------------- shared memory union ----------------
struct SmSt {
    float alpha[512];
    float h[256];
    float eu[512], ratio[512], beta[512];
    float ctx[256];
    float part[1024];
    float w8[32];
};
struct __align__(16) SmGm {
    unsigned long long Ap[128][10];
    unsigned long long Bp[128][10];
};
union SmU {
    SmSt st;
    SmGm gm;
};

// ---------------- helpers ----------------
__device__ __forceinline__ float warp_sum(float v) {
#pragma unroll
    for (int s = 16; s; s >>= 1) v += __shfl_xor_sync(0xffffffffu, v, s);
    return v;
}
__device__ __forceinline__ float tanh_fast(float x) {   // exact-ish (RNN/attn path)
    float e = __expf(2.0f * x);
    return 1.0f - __fdividef(2.0f, e + 1.0f);
}
__device__ __forceinline__ float tanh_hw(float x) {     // 1-MUFU HW tanh (energy path)
    float y;
    asm("tanh.approx.f32 %0, %1;" : "=f"(y) : "f"(x));
    return y;
}
__device__ __forceinline__ float sigmoid_fast(float x) {
    return __fdividef(1.0f, 1.0f + __expf(-x));
}
__device__ __forceinline__ unsigned long long pk2(float lo, float hi) {
    unsigned long long r;
    asm("mov.b64 %0, {%1, %2};" : "=l"(r) : "f"(lo), "f"(hi));
    return r;
}
__device__ __forceinline__ void fma2(unsigned long long& acc, unsigned long long a,
                                     unsigned long long b) {
    asm("fma.rn.f32x2 %0, %1, %2, %0;" : "+l"(acc) : "l"(a), "l"(b));
}
__device__ __forceinline__ void unpack2(unsigned long long v, float& lo, float& hi) {
    asm("mov.b64 {%0, %1}, %2;" : "=f"(lo), "=f"(hi) : "l"(v));
}

// exclusive prefix over 256 per-thread pair-sums
__device__ __forceinline__ float pair_excl(float ps, float* s_w8) {
    int tid = threadIdx.x, lane = tid & 31, wid = tid >> 5;
    float s = ps;
#pragma unroll
    for (int d = 1; d < 32; d <<= 1) {
        float n = __shfl_up_sync(0xffffffffu, s, d);
        if (lane >= d) s += n;
    }
    __syncthreads();
    if (lane == 31) s_w8[wid] = s;
    __syncthreads();
    if (tid < 32) {
        float v = (lane < 8) ? s_w8[lane] : 0.0f;
#pragma unroll
        for (int d = 1; d < 8; d <<= 1) {
            float n = __shfl_up_sync(0xffffffffu, v, d);
            if (lane >= d) v += n;
        }
        if (lane < 8) s_w8[lane] = v;
    }
    __syncthreads();
    float woff = wid ? s_w8[wid - 1] : 0.0f;
    return woff + (s - ps);
}

__device__ __forceinline__ float max512(float m, float* s_w8) {
    int tid = threadIdx.x, lane = tid & 31, wid = tid >> 5;
#pragma unroll
    for (int s = 16; s; s >>= 1) m = fmaxf(m, __shfl_xor_sync(0xffffffffu, m, s));
    __syncthreads();
    if (lane == 0) s_w8[wid] = m;
    __syncthreads();
    if (tid < 32) {
        float v = (lane < 8) ? s_w8[lane] : -1e30f;
#pragma unroll
        for (int s = 4; s; s >>= 1) v = fmaxf(v, __shfl_xor_sync(0xffffffffu, v, s));
        if (lane == 0) s_w8[0] = v;
    }
    __syncthreads();
    return s_w8[0];
}

// y[o=tid] = sum_{k<256} x[k] * WT[k*256+o]
__device__ __forceinline__ float gemv256(const float* __restrict__ WT,
                                         const float* __restrict__ x, float* s_part) {
    int tid = threadIdx.x;
    int j = tid & 63, kq = tid >> 6;
    __syncthreads();
    const float4* Wp = reinterpret_cast<const float4*>(WT);
    float4 acc = make_float4(0.f, 0.f, 0.f, 0.f);
    int k0 = kq * 64;
#pragma unroll 8
    for (int k = k0; k < k0 + 64; ++k) {
        float f = x[k];
        float4 w = Wp[(size_t)k * 64 + j];
        acc.x = fmaf(f, w.x, acc.x);
        acc.y = fmaf(f, w.y, acc.y);
        acc.z = fmaf(f, w.z, acc.z);
        acc.w = fmaf(f, w.w, acc.w);
    }
    reinterpret_cast<float4*>(s_part)[kq * 64 + j] = acc;
    __syncthreads();
    return s_part[tid] + s_part[256 + tid] + s_part[512 + tid] + s_part[768 + tid];
}

__device__ __forceinline__ void publish_exch(unsigned* flag, unsigned v) {
    __threadfence();
    __syncthreads();
    if (threadIdx.x == 0) atomicExch(flag, v);
}
__device__ __forceinline__ void spin_cta(const unsigned* flag, unsigned v) {
    if (threadIdx.x == 0) {
        const volatile unsigned* f = (const volatile unsigned*)flag;
        while (*f < v) {}
    }
    __syncthreads();
}
// poll n flags concurrently (threads 0..n-1), one barrier
__device__ __forceinline__ void spin_cta_multi(unsigned* base, int i0, int n, unsigned v) {
    if (threadIdx.x < (unsigned)n) {
        const volatile unsigned* f = (const volatile unsigned*)(base + i0 + threadIdx.x);
        while (*f < v) {}
    }
    __syncthreads();
}

// ---------------- GEMM tile: C[128,128] = A[128xK] @ B[128xK]^T + bias, K=256 -------
template <bool REMAP, bool ACG>
__device__ void gemm_tile(const float* __restrict__ A, const float* __restrict__ Bw,
                          const float* __restrict__ bias, float* __restrict__ C, int bm,
                          int bn, int N, SmGm* sg) {
    const int K = 256;
    int tid = threadIdx.x, tx = tid & 15, ty = tid >> 4;
    int lrow = tid >> 1, lk = (tid & 1) * 8, kb = (tid & 1) * 4;
    const float* Aptr = A + (size_t)(bm + lrow) * K + lk;
    const float* Bptr = Bw + (size_t)(bn + lrow) * K + lk;

    unsigned long long acc[8][8];
#pragma unroll
    for (int r = 0; r < 8; ++r)
#pragma unroll
        for (int c = 0; c < 8; ++c) acc[r][c] = 0ull;

    float4 fa0, fa1, fb0, fb1;
    if (ACG) {
        fa0 = __ldcg((const float4*)Aptr);
        fa1 = __ldcg((const float4*)(Aptr + 4));
    } else {
        fa0 = *(const float4*)Aptr;
        fa1 = *(const float4*)(Aptr + 4);
    }
    fb0 = *(const float4*)Bptr;
    fb1 = *(const float4*)(Bptr + 4);

#pragma unroll 1
    for (int k0 = 0; k0 < K; k0 += 16) {
        sg->Ap[lrow][kb + 0] = pk2(fa0.x, fa0.y);
        sg->Ap[lrow][kb + 1] = pk2(fa0.z, fa0.w);
        sg->Ap[lrow][kb + 2] = pk2(fa1.x, fa1.y);
        sg->Ap[lrow][kb + 3] = pk2(fa1.z, fa1.w);
        sg->Bp[lrow][kb + 0] = pk2(fb0.x, fb0.y);
        sg->Bp[lrow][kb + 1] = pk2(fb0.z, fb0.w);
        sg->Bp[lrow][kb + 2] = pk2(fb1.x, fb1.y);
        sg->Bp[lrow][kb + 3] = pk2(fb1.z, fb1.w);
        __syncthreads();
        if (k0 + 16 < K) {
            if (ACG) {
                fa0 = __ldcg((const float4*)(Aptr + k0 + 16));
                fa1 = __ldcg((const float4*)(Aptr + k0 + 20));
            } else {
                fa0 = *(const float4*)(Aptr + k0 + 16);
                fa1 = *(const float4*)(Aptr + k0 + 20);
            }
            fb0 = *(const float4*)(Bptr + k0 + 16);
            fb1 = *(const float4*)(Bptr + k0 + 20);
        }
#pragma unroll
        for (int u = 0; u < 4; ++u) {
            ulonglong2 a2[8], b2[8];
#pragma unroll
            for (int r = 0; r < 8; ++r)
                a2[r] = *reinterpret_cast<const ulonglong2*>(&sg->Ap[ty + 16 * r][2 * u]);
#pragma unroll
            for (int c = 0; c < 8; ++c)
                b2[c] = *reinterpret_cast<const ulonglong2*>(&sg->Bp[tx + 16 * c][2 * u]);
#pragma unroll
            for (int r = 0; r < 8; ++r)
#pragma unroll
                for (int c = 0; c < 8; ++c) {
                    fma2(acc[r][c], a2[r].x, b2[c].x);
                    fma2(acc[r][c], a2[r].y, b2[c].y);
                }
        }
        __syncthreads();
    }

    float bb[8];
#pragma unroll
    for (int c = 0; c < 8; ++c) bb[c] = __ldg(&bias[bn + tx + 16 * c]);
#pragma unroll
    for (int r = 0; r < 8; ++r) {
        int row = bm + ty + 16 * r;
        float* crow;
        if (REMAP) {
            crow = C + (size_t)((row & 31) * TDEC + (row >> 5)) * N;
        } else {
            crow = C + (size_t)row * N;
        }
#pragma unroll
        for (int c = 0; c < 8; ++c) {
            float lo, hi;
            unpack2(acc[r][c], lo, hi);
            crow[bn + tx + 16 * c] = lo + hi + bb[c];
        }
    }
}

// ---------------- init ----------------
__global__ void k_init(const float* __restrict__ W_ih, const float* __restrict__ b_ih,
                       const float* __restrict__ W_hh, const float* __restrict__ b_hh,
                       const float* __restrict__ Vm, const float* __restrict__ Vc,
                       const float* __restrict__ W_comb, const float* __restrict__ Wm,
                       const float* __restrict__ Wc, const float* __restrict__ bm,
                       const float* __restrict__ bc, const float* __restrict__ vvm,
                       const float* __restrict__ gm, const float* __restrict__ vbm,
                       const float* __restrict__ rm, const float* __restrict__ vvc,
                       const float* __restrict__ gc, const float* __restrict__ vbc,
                       const float* __restrict__ rc) {
    int bidx = blockIdx.x, tid = threadIdx.x;
    if (bidx < 96) {
        for (int idx = bidx * 256 + tid; idx < 524288; idx += 96 * 256) {
            if (idx < 65536) {
                int k = idx >> 8, o = idx & 255;
                g_WihT[idx] = W_ih[o * 256 + k];
            } else if (idx < 131072) {
                int r = idx - 65536;
                int k = r >> 8, o = r & 255;
                g_WhhT[r] = W_hh[o * 256 + k];
            } else if (idx < 196608) {
                int r = idx - 131072;
                int k = r >> 8, o = r & 255;
                g_VmT[r] = Vm[o * 256 + k];
            } else if (idx < 262144) {
                int r = idx - 196608;
                int k = r >> 8, o = r & 255;
                g_VcT[r] = Vc[o * 256 + k];
            } else if (idx < 393216) {
                int r = idx - 262144;
                int k = r >> 8, o = r & 255;
                g_WcombT[r] = W_comb[o * 512 + k];
            } else {
                int r = idx - 393216;
                int o = r >> 8, k = r & 255;
                g_Wmc[r] = (o < 256) ? Wm[o * 256 + k] : Wc[(o - 256) * 256 + k];
            }
        }
    } else {
        __shared__ float red[256];
        for (int i = tid; i < B_ * 32; i += 256) g_flags[i] = 0u;
        if (tid < TDEC) g_scnt[tid] = 0u;
        if (tid == 0) g_tile = 0u;
        g_bmc[tid] = bm[tid];
        g_bmc[256 + tid] = bc[tid];
        float v = vvm[tid];
        red[tid] = v * v;
        __syncthreads();
        for (int s = 128; s > 0; s >>= 1) {
            if (tid < s) red[tid] += red[tid + s];
            __syncthreads();
        }
        float nm = sqrtf(red[0]);
        __syncthreads();
        g_wm[tid] = vvm[tid] * gm[0] / nm;
        float v2 = vvc[tid];
        red[tid] = v2 * v2;
        __syncthreads();
        for (int s = 128; s > 0; s >>= 1) {
            if (tid < s) red[tid] += red[tid + s];
            __syncthreads();
        }
        float nc = sqrtf(red[0]);
        __syncthreads();
        g_wc[tid] = vvc[tid] * gc[0] / nc;
        g_biasr[tid] = b_ih[tid] + b_hh[tid];
        if (tid == 0) {
            g_cst[0] = vbm[0] + rm[0];
            g_cst[1] = vbc[0] + rc[0];
        }
    }
}

// ---------------- token projections ----------------
__global__ __launch_bounds__(256) void k_xw(const int* __restrict__ dec,
                                            const float* __restrict__ emb) {
    __shared__ float s_x[256];
    __shared__ float s_part[1024];
    int t = blockIdx.x, b = blockIdx.y, tid = threadIdx.x;
    int tok = (t == 0) ? SOS_ : dec[b * TDEC + (t - 1)];
    s_x[tid] = __ldg(&emb[(size_t)tok * DIM + tid]);
    float y = gemv256(g_WihT, s_x, s_part) + g_biasr[tid];
    g_xw[((size_t)b * (TDEC + 1) + t) * DIM + tid] = y;
}

// ---------------- fused encoder projection ----------------
__global__ __launch_bounds__(256, 1) void k_gemm_enc(const float* __restrict__ enc) {
    __shared__ SmGm sg;
    gemm_tile<false, false>(enc, g_Wmc, g_bmc, g_encW, blockIdx.y * 128, blockIdx.x * 128,
                            512, &sg);
}

// ---------------- energy over [lo,hi) for batch b at step t (workers only) ----------
__device__ __forceinline__ void energy_range(int b, int lo, int hi, int t,
                                             const float* __restrict__ noise,
                                             const float* rhm, const float* rhc,
                                             const float* rwm, const float* rwc, float cm,
                                             float cc, float* out_p, float* out_ec) {
    int tid = threadIdx.x, wid = tid >> 5, lane = tid & 31;
    const size_t base = (size_t)b * TENC;
#pragma unroll 1
    for (int tt = lo + wid; tt < hi; tt += 8) {
        const float4* row4 = reinterpret_cast<const float4*>(g_encW + (base + tt) * 512);
        float4 m0 = row4[lane * 2], m1 = row4[lane * 2 + 1];
        float4 c0 = row4[64 + lane * 2], c1 = row4[64 + lane * 2 + 1];
        float mv[8] = {m0.x, m0.y, m0.z, m0.w, m1.x, m1.y, m1.z, m1.w};
        float cv[8] = {c0.x, c0.y, c0.z, c0.w, c1.x, c1.y, c1.z, c1.w};
        float am = 0.f, ac = 0.f;
#pragma unroll
        for (int j = 0; j < 8; ++j) {
            am = fmaf(tanh_hw(mv[j] + rhm[j]), rwm[j], am);
            ac = fmaf(tanh_hw(cv[j] + rhc[j]), rwc[j], ac);
        }
        am = warp_sum(am);
        ac = warp_sum(ac);
        if (lane == 0) {
            float pp =
                sigmoid_fast(am + cm + __ldg(&noise[((size_t)t * B_ + b) * TENC + tt]));
            __stcg(&out_p[tt], pp);
            __stcg(&out_ec[tt], ac + cc);
        }
    }
}

// ---------------- persistent kernel: steps + work-steal vocab GEMM ----------------
// 148 CTAs. CTA<128: b=cta&31, q=cta>>5. q0 = post (no energy), q1/q2/q3 = energy
// thirds + (hVc / uch / hVm). CTA>=128: GEMM helpers. All drain the tile queue.
__global__ __launch_bounds__(256, 1) void k_steps(
    const float* __restrict__ enc, const float* __restrict__ h0,
    const float* __restrict__ noise, const float* __restrict__ Wproj,
    const float* __restrict__ bproj, float* __restrict__ out) {
    __shared__ SmU su;
    __shared__ int s_idx;

    int tid = threadIdx.x, cta = blockIdx.x;

    if (cta < 128) {
        int b = cta & 31, q = cta >> 5;
        int lane = tid & 31;
        int a0 = lane * 8;

        if (q == 0) {
            // ---- POST ----
            su.st.h[tid] = h0[b * DIM + tid];
            su.st.alpha[tid] = (tid == 0) ? 1.0f : 0.0f;
            su.st.alpha[256 + tid] = 0.0f;
            float yh = gemv256(g_WhhT, su.st.h, su.st.part);
            float hn = tanh_fast(yh + __ldg(&g_xw[((size_t)b * (TDEC + 1)) * DIM + tid]));
            __syncthreads();
            su.st.h[tid] = hn;
            __stcg(&g_h[0][b * DIM + tid], hn);
            publish_exch(FLG(b, 0), 1u);

#pragma unroll 1
            for (int t = 0; t < TDEC; ++t) {
                int par = t & 1;
                // 1) recurrence first: H_{t+1} published before the heavy work
                if (t < TDEC - 1) {
                    float yh2 = gemv256(g_WhhT, su.st.h, su.st.part);
                    float hn2 = tanh_fast(
                        yh2 + __ldg(&g_xw[((size_t)b * (TDEC + 1) + t + 1) * DIM + tid]));
                    __syncthreads();
                    su.st.h[tid] = hn2;
                    __stcg(&g_h[1 - par][b * DIM + tid], hn2);
                    publish_exch(FLG(b, 0), (unsigned)(t + 2));
                }
                // 2) all three workers done with energy(t)?
                spin_cta_multi(FLG(b, 0), 4, 3, (unsigned)(t + 1));

                // 3) alpha scans
                int j0 = 2 * tid, j1 = 2 * tid + 1;
                float p0 = __ldcg(&g_p[par][b * TENC + j0]);
                float p1 = __ldcg(&g_p[par][b * TENC + j1]);
                float l0 = __logf(fminf(fmaxf(1.0f - p0, 1e-10f), 1.0f));
                float l1 = __logf(fminf(fmaxf(1.0f - p1, 1e-10f), 1.0f));
                float eP = pair_excl(l0 + l1, su.st.w8);
                float cp0 = __expf(eP);
                float cp1 = __expf(eP + l0);
                float A0 = su.st.alpha[j0], A1 = su.st.alpha[j1];
                float r0 = __fdividef(A0, fmaxf(cp0, 1e-10f));
                float r1 = __fdividef(A1, fmaxf(cp1, 1e-10f));
                float eS = pair_excl(r0 + r1, su.st.w8);
                float na0 = p0 * cp0 * (eS + r0);
                float na1 = p1 * cp1 * (eS + r0 + r1);
                su.st.alpha[j0] = na0;
                su.st.alpha[j1] = na1;

                // 4) chunkwise beta
                float e0 = __ldcg(&g_ecb[par][b * TENC + j0]);
                float e1 = __ldcg(&g_ecb[par][b * TENC + j1]);
                float mx = max512(fmaxf(e0, e1), su.st.w8);
                float eu0 = __expf(e0 - mx), eu1 = __expf(e1 - mx);
                su.st.eu[j0] = eu0;
                su.st.eu[j1] = eu1;
                __syncthreads();
                float d0 = 0.0f, d1 = 0.0f;
#pragma unroll
                for (int k = 0; k < 8; ++k) {
                    int q0i = j0 - k, q1i = j1 - k;
                    if (q0i >= 0) d0 += su.st.eu[q0i];
                    if (q1i >= 0) d1 += su.st.eu[q1i];
                }
                su.st.ratio[j0] = __fdividef(na0, fmaxf(d0, 1e-10f));
                su.st.ratio[j1] = __fdividef(na1, fmaxf(d1, 1e-10f));
                __syncthreads();
                float b0 = 0.0f, b1 = 0.0f;
#pragma unroll
                for (int k = 0; k < 8; ++k) {
                    int q0i = j0 + k, q1i = j1 + k;
                    if (q0i < TENC) b0 += su.st.ratio[q0i];
                    if (q1i < TENC) b1 += su.st.ratio[q1i];
                }
                su.st.beta[j0] = eu0 * b0;
                su.st.beta[j1] = eu1 * b1;
                __syncthreads();

                // 5) context = beta @ enc[b]
                {
                    int jj = tid & 63, tq4 = tid >> 6;
                    const float4* ep = reinterpret_cast<const float4*>(enc) +
                                       (size_t)(b * TENC + tq4 * 128) * (DIM / 4) + jj;
                    float4 acc = make_float4(0.f, 0.f, 0.f, 0.f);
#pragma unroll 4
                    for (int ttt = 0; ttt < 128; ++ttt) {
                        float f = su.st.beta[tq4 * 128 + ttt];
                        float4 e4 = ep[(size_t)ttt * 64];
                        acc.x = fmaf(f, e4.x, acc.x);
                        acc.y = fmaf(f, e4.y, acc.y);
                        acc.z = fmaf(f, e4.z, acc.z);
                        acc.w = fmaf(f, e4.w, acc.w);
                    }
                    reinterpret_cast<float4*>(su.st.part)[tq4 * 64 + jj] = acc;
                }
                __syncthreads();
                su.st.ctx[tid] = su.st.part[tid] + su.st.part[256 + tid] +
                                 su.st.part[512 + tid] + su.st.part[768 + tid];

                // 6) attn = tanh(Wcomb_ctx@ctx + uch(t))
                float av = gemv256(g_WcombT, su.st.ctx, su.st.part);
                spin_cta(FLG(b, 3), (unsigned)(t + 1));
                float at = tanh_fast(av + __ldcg(&g_uch[par][b * DIM + tid]));
                __stcg(&g_attn[((size_t)t * B_ + b) * DIM + tid], at);
                __threadfence();
                __syncthreads();
                if (tid == 0) atomicAdd(&g_scnt[t], 1u);
            }
        } else {
            // ---- WORKERS ----
            int lo = (q == 1) ? 0 : (q == 2) ? 171 : 342;
            int hi = (q == 1) ? 171 : (q == 2) ? 342 : 512;
            float cm = g_cst[0], cc = g_cst[1];
            float rwm[8], rwc[8];
#pragma unroll
            for (int j = 0; j < 8; ++j) {
                rwm[j] = __ldg(&g_wm[a0 + j]);
                rwc[j] = __ldg(&g_wc[a0 + j]);
            }
            // prologue: hV(0)
            if (q == 1) {
                spin_cta(FLG(b, 0), 1u);
                su.st.ctx[tid] = __ldcg(&g_h[0][b * DIM + tid]);
                float yc = gemv256(g_VcT, su.st.ctx, su.st.part);
                __stcg(&g_hVc[0][b * DIM + tid], yc);
                publish_exch(FLG(b, 2), 1u);
            } else if (q == 3) {
                spin_cta(FLG(b, 0), 1u);
                su.st.ctx[tid] = __ldcg(&g_h[0][b * DIM + tid]);
                float ym = gemv256(g_VmT, su.st.ctx, su.st.part);
                __stcg(&g_hVm[0][b * DIM + tid], ym);
                publish_exch(FLG(b, 1), 1u);
            }

#pragma unroll 1
            for (int t = 0; t < TDEC; ++t) {
                int par = t & 1;
                spin_cta_multi(FLG(b, 0), 1, 2, (unsigned)(t + 1));   // hVm & hVc ready
                float rhm[8], rhc[8];
                {
                    const float* hm = g_hVm[par] + b * DIM + a0;
                    const float* hc = g_hVc[par] + b * DIM + a0;
                    float4 v0 = __ldcg(reinterpret_cast<const float4*>(hm));
                    float4 v1 = __ldcg(reinterpret_cast<const float4*>(hm + 4));
                    rhm[0] = v0.x; rhm[1] = v0.y; rhm[2] = v0.z; rhm[3] = v0.w;
                    rhm[4] = v1.x; rhm[5] = v1.y; rhm[6] = v1.z; rhm[7] = v1.w;
                    float4 w0 = __ldcg(reinterpret_cast<const float4*>(hc));
                    float4 w1 = __ldcg(reinterpret_cast<const float4*>(hc + 4));
                    rhc[0] = w0.x; rhc[1] = w0.y; rhc[2] = w0.z; rhc[3] = w0.w;
                    rhc[4] = w1.x; rhc[5] = w1.y; rhc[6] = w1.z; rhc[7] = w1.w;
                }
                energy_range(b, lo, hi, t, noise, rhm, rhc, rwm, rwc, cm, cc,
                             g_p[par] + b * TENC, g_ecb[par] + b * TENC);
                publish_exch(FLG(b, 3 + q), (unsigned)(t + 1));
                if (q == 2) {
                    // uch(t) = Wcomb_h @ H_t (parity slot t&1)
                    su.st.ctx[tid] = __ldcg(&g_h[par][b * DIM + tid]);
                    float u = gemv256(g_WcombT + 256 * 256, su.st.ctx, su.st.part);
                    __stcg(&g_uch[par][b * DIM + tid], u);
                    publish_exch(FLG(b, 3), (unsigned)(t + 1));
                } else if (q == 1 && t < TDEC - 1) {
                    spin_cta(FLG(b, 0), (unsigned)(t + 2));
                    su.st.ctx[tid] = __ldcg(&g_h[1 - par][b * DIM + tid]);
                    float yc = gemv256(g_VcT, su.st.ctx, su.st.part);
                    __stcg(&g_hVc[1 - par][b * DIM + tid], yc);
                    publish_exch(FLG(b, 2), (unsigned)(t + 2));
                } else if (q == 3 && t < TDEC - 1) {
                    spin_cta(FLG(b, 0), (unsigned)(t + 2));
                    su.st.ctx[tid] = __ldcg(&g_h[1 - par][b * DIM + tid]);
                    float ym = gemv256(g_VmT, su.st.ctx, su.st.part);
                    __stcg(&g_hVm[1 - par][b * DIM + tid], ym);
                    publish_exch(FLG(b, 1), (unsigned)(t + 2));
                }
            }
        }
    }

    // ---- work-steal vocab GEMM: tiles gated on step completion ----
    for (;;) {
        __syncthreads();
        if (tid == 0) s_idx = (int)atomicAdd(&g_tile, 1u);
        __syncthreads();
        int idx = s_idx;
        if (idx >= NTILE) break;
        int m = idx / (VOCAB_ / 128);
        int n = idx - m * (VOCAB_ / 128);
        if (tid == 0) {
            const volatile unsigned* f = &g_scnt[4 * m + 3];
            while (*f < 32u) __nanosleep(256);
        }
        __syncthreads();
        __threadfence();
        gemm_tile<true, true>(g_attn, Wproj, bproj, out, m * 128, n * 128, VOCAB_,
                              &su.gm);
    }
}

// ---------------- launch ----------------
extern "C" void kernel_launch(void* const* d_in, const int* in_sizes, int n_in, void* d_out,
                              int out_size) {
    (void)in_sizes;
    (void)n_in;
    (void)out_size;
    const float* enc = (const float*)d_in[0];
    const int* dec = (const int*)d_in[1];
    const float* h0 = (const float*)d_in[2];
    const float* noise = (const float*)d_in[3];
    const float* emb = (const float*)d_in[4];
    const float* W_ih = (const float*)d_in[5];
    const float* b_ih = (const float*)d_in[6];
    const float* W_hh = (const float*)d_in[7];
    const float* b_hh = (const float*)d_in[8];
    const float* Wm = (const float*)d_in[9];
    const float* Vm = (const float*)d_in[10];
    const float* bm = (const float*)d_in[11];
    const float* vvm = (const float*)d_in[12];
    const float* gm = (const float*)d_in[13];
    const float* vbm = (const float*)d_in[14];
    const float* rm = (const float*)d_in[15];
    const float* Wc = (const float*)d_in[16];
    const float* Vc = (const float*)d_in[17];
    const float* bc = (const float*)d_in[18];
    const float* vvc = (const float*)d_in[19];
    const float* gc = (const float*)d_in[20];
    const float* vbc = (const float*)d_in[21];
    const float* rc = (const float*)d_in[22];
    const float* W_comb = (const float*)d_in[23];
    const float* W_proj = (const float*)d_in[24];
    const float* b_proj = (const float*)d_in[25];
    float* out = (float*)d_out;

    k_init<<<97, 256>>>(W_ih, b_ih, W_hh, b_hh, Vm, Vc, W_comb, Wm, Wc, bm, bc, vvm, gm,
                        vbm, rm, vvc, gc, vbc, rc);
    k_xw<<<dim3(TDEC + 1, B_), 256>>>(dec, emb);
    k_gemm_enc<<<dim3(512 / 128, (B_ * TENC) / 128), 256>>>(enc);
    k_steps<<<148, 256>>>(enc, h0, noise, W_proj, b_proj, out);
}

// round 14
// speedup vs baseline: 1.5188x; 1.0239x over previous
#include <cuda_runtime.h>
#include <cuda_bf16.h>
#include <cstdint>

#define B_      32
#define TENC    512
#define TDEC    32
#define DIM     256
#define VOCAB_  32000
#define SOS_    1
#define NTILE_E 1024                       // enc GEMM: (16384/64) * (512/128)
#define NTILE_V ((TDEC * B_ / 64) * (VOCAB_ / 128))   // 16 * 250 = 4000

// ---------------- device scratch (parity double-buffered per-step data) ----------------
__device__ float g_encW[B_ * TENC * 512];
__device__ float g_hVm[2][B_ * DIM];
__device__ float g_hVc[2][B_ * DIM];
__device__ float g_p[2][B_ * TENC];
__device__ float g_ecb[2][B_ * TENC];
__device__ float g_uch[2][B_ * DIM];
__device__ float g_h[2][B_ * DIM];
__device__ float g_attn[TDEC * B_ * DIM];  // row = t*B + b
__device__ float g_xw[B_ * (TDEC + 1) * DIM];
__device__ float g_WihT[256 * 256];
__device__ float g_WhhT[256 * 256];
__device__ float g_VmT[256 * 256];
__device__ float g_VcT[256 * 256];
__device__ float g_WcombT[512 * 256];
__device__ float g_Wmc[512 * 256];
__device__ float g_bmc[512];
__device__ float g_biasr[256];
__device__ float g_wm[256];
__device__ float g_wc[256];
__device__ float g_cst[2];
__device__ unsigned g_flags[B_ * 32];   // 0=hgen 1=hvm 2=hvc 3=uch 4/5/6=energy workers
__device__ unsigned g_scnt[TDEC];
__device__ unsigned g_tile_enc;
__device__ unsigned g_encdone;
__device__ unsigned g_tile;
#define FLG(b, i) (&g_flags[(b) * 32 + (i)])

// ---------------- shared memory union ----------------
struct SmSt {
    float alpha[512];
    float h[256];
    float eu[512], ratio[512], beta[512];
    float ctx[256];
    float part[1024];
    float w8[32];
};
struct __align__(16) SmGm {
    unsigned long long Ap[64][10];
    unsigned long long Bp[128][10];
};
union SmU {
    SmSt st;
    SmGm gm;
};

// ---------------- helpers ----------------
__device__ __forceinline__ float warp_sum(float v) {
#pragma unroll
    for (int s = 16; s; s >>= 1) v += __shfl_xor_sync(0xffffffffu, v, s);
    return v;
}
__device__ __forceinline__ float tanh_fast(float x) {
    float e = __expf(2.0f * x);
    return 1.0f - __fdividef(2.0f, e + 1.0f);
}
__device__ __forceinline__ float tanh_hw(float x) {
    float y;
    asm("tanh.approx.f32 %0, %1;" : "=f"(y) : "f"(x));
    return y;
}
__device__ __forceinline__ float sigmoid_fast(float x) {
    return __fdividef(1.0f, 1.0f + __expf(-x));
}
__device__ __forceinline__ unsigned long long pk2(float lo, float hi) {
    unsigned long long r;
    asm("mov.b64 %0, {%1, %2};" : "=l"(r) : "f"(lo), "f"(hi));
    return r;
}
__device__ __forceinline__ void fma2(unsigned long long& acc, unsigned long long a,
                                     unsigned long long b) {
    asm("fma.rn.f32x2 %0, %1, %2, %0;" : "+l"(acc) : "l"(a), "l"(b));
}
__device__ __forceinline__ void unpack2(unsigned long long v, float& lo, float& hi) {
    asm("mov.b64 {%0, %1}, %2;" : "=f"(lo), "=f"(hi) : "l"(v));
}

__device__ __forceinline__ float pair_excl(float ps, float* s_w8) {
    int tid = threadIdx.x, lane = tid & 31, wid = tid >> 5;
    float s = ps;
#pragma unroll
    for (int d = 1; d < 32; d <<= 1) {
        float n = __shfl_up_sync(0xffffffffu, s, d);
        if (lane >= d) s += n;
    }
    __syncthreads();
    if (lane == 31) s_w8[wid] = s;
    __syncthreads();
    if (tid < 32) {
        float v = (lane < 8) ? s_w8[lane] : 0.0f;
#pragma unroll
        for (int d = 1; d < 8; d <<= 1) {
            float n = __shfl_up_sync(0xffffffffu, v, d);
            if (lane >= d) v += n;
        }
        if (lane < 8) s_w8[lane] = v;
    }
    __syncthreads();
    float woff = wid ? s_w8[wid - 1] : 0.0f;
    return woff + (s - ps);
}

__device__ __forceinline__ float max512(float m, float* s_w8) {
    int tid = threadIdx.x, lane = tid & 31, wid = tid >> 5;
#pragma unroll
    for (int s = 16; s; s >>= 1) m = fmaxf(m, __shfl_xor_sync(0xffffffffu, m, s));
    __syncthreads();
    if (lane == 0) s_w8[wid] = m;
    __syncthreads();
    if (tid < 32) {
        float v = (lane < 8) ? s_w8[lane] : -1e30f;
#pragma unroll
        for (int s = 4; s; s >>= 1) v = fmaxf(v, __shfl_xor_sync(0xffffffffu, v, s));
        if (lane == 0) s_w8[0] = v;
    }
    __syncthreads();
    return s_w8[0];
}

__device__ __forceinline__ float gemv256(const float* __restrict__ WT,
                                         const float* __restrict__ x, float* s_part) {
    int tid = threadIdx.x;
    int j = tid & 63, kq = tid >> 6;
    __syncthreads();
    const float4* Wp = reinterpret_cast<const float4*>(WT);
    float4 acc = make_float4(0.f, 0.f, 0.f, 0.f);
    int k0 = kq * 64;
#pragma unroll 8
    for (int k = k0; k < k0 + 64; ++k) {
        float f = x[k];
        float4 w = Wp[(size_t)k * 64 + j];
        acc.x = fmaf(f, w.x, acc.x);
        acc.y = fmaf(f, w.y, acc.y);
        acc.z = fmaf(f, w.z, acc.z);
        acc.w = fmaf(f, w.w, acc.w);
    }
    reinterpret_cast<float4*>(s_part)[kq * 64 + j] = acc;
    __syncthreads();
    return s_part[tid] + s_part[256 + tid] + s_part[512 + tid] + s_part[768 + tid];
}

__device__ __forceinline__ void publish_exch(unsigned* flag, unsigned v) {
    __threadfence();
    __syncthreads();
    if (threadIdx.x == 0) atomicExch(flag, v);
}
__device__ __forceinline__ void spin_cta(const unsigned* flag, unsigned v) {
    if (threadIdx.x == 0) {
        const volatile unsigned* f = (const volatile unsigned*)flag;
        while (*f < v) {}
    }
    __syncthreads();
}
__device__ __forceinline__ void spin_cta_multi(unsigned* base, int i0, int n, unsigned v) {
    if (threadIdx.x < (unsigned)n) {
        const volatile unsigned* f = (const volatile unsigned*)(base + i0 + threadIdx.x);
        while (*f < v) {}
    }
    __syncthreads();
}

// ---------------- GEMM tile: C[64,128] = A[64xK] @ B[128xK]^T + bias, K=256 --------
template <bool REMAP, bool ACG>
__device__ void gemm_tile64(const float* __restrict__ A, const float* __restrict__ Bw,
                            const float* __restrict__ bias, float* __restrict__ C, int bm,
                            int bn, int N, SmGm* sg) {
    const int K = 256;
    int tid = threadIdx.x, tx = tid & 15, ty = tid >> 4;
    int lrowA = tid >> 2, kbA = (tid & 3) * 2;
    int lrowB = tid >> 1, kbB = (tid & 1) * 4;
    const float* Aptr = A + (size_t)(bm + lrowA) * K + (tid & 3) * 4;
    const float* Bptr = Bw + (size_t)(bn + lrowB) * K + (tid & 1) * 8;

    unsigned long long acc[4][8];
#pragma unroll
    for (int r = 0; r < 4; ++r)
#pragma unroll
        for (int c = 0; c < 8; ++c) acc[r][c] = 0ull;

    float4 fa, fb0, fb1;
    fa = ACG ? __ldcg((const float4*)Aptr) : *(const float4*)Aptr;
    fb0 = *(const float4*)Bptr;
    fb1 = *(const float4*)(Bptr + 4);

#pragma unroll 1
    for (int k0 = 0; k0 < K; k0 += 16) {
        sg->Ap[lrowA][kbA + 0] = pk2(fa.x, fa.y);
        sg->Ap[lrowA][kbA + 1] = pk2(fa.z, fa.w);
        sg->Bp[lrowB][kbB + 0] = pk2(fb0.x, fb0.y);
        sg->Bp[lrowB][kbB + 1] = pk2(fb0.z, fb0.w);
        sg->Bp[lrowB][kbB + 2] = pk2(fb1.x, fb1.y);
        sg->Bp[lrowB][kbB + 3] = pk2(fb1.z, fb1.w);
        __syncthreads();
        if (k0 + 16 < K) {
            fa = ACG ? __ldcg((const float4*)(Aptr + k0 + 16))
                     : *(const float4*)(Aptr + k0 + 16);
            fb0 = *(const float4*)(Bptr + k0 + 16);
            fb1 = *(const float4*)(Bptr + k0 + 20);
        }
#pragma unroll
        for (int u = 0; u < 4; ++u) {
            ulonglong2 a2[4], b2[8];
#pragma unroll
            for (int r = 0; r < 4; ++r)
                a2[r] = *reinterpret_cast<const ulonglong2*>(&sg->Ap[ty + 16 * r][2 * u]);
#pragma unroll
            for (int c = 0; c < 8; ++c)
                b2[c] = *reinterpret_cast<const ulonglong2*>(&sg->Bp[tx + 16 * c][2 * u]);
#pragma unroll
            for (int r = 0; r < 4; ++r)
#pragma unroll
                for (int c = 0; c < 8; ++c) {
                    fma2(acc[r][c], a2[r].x, b2[c].x);
                    fma2(acc[r][c], a2[r].y, b2[c].y);
                }
        }
        __syncthreads();
    }

    float bb[8];
#pragma unroll
    for (int c = 0; c < 8; ++c) bb[c] = __ldg(&bias[bn + tx + 16 * c]);
#pragma unroll
    for (int r = 0; r < 4; ++r) {
        int row = bm + ty + 16 * r;
        float* crow;
        if (REMAP) {
            crow = C + (size_t)((row & 31) * TDEC + (row >> 5)) * N;
        } else {
            crow = C + (size_t)row * N;
        }
#pragma unroll
        for (int c = 0; c < 8; ++c) {
            float lo, hi;
            unpack2(acc[r][c], lo, hi);
            crow[bn + tx + 16 * c] = lo + hi + bb[c];
        }
    }
}

// ---------------- init ----------------
__global__ void k_init(const float* __restrict__ W_ih, const float* __restrict__ b_ih,
                       const float* __restrict__ W_hh, const float* __restrict__ b_hh,
                       const float* __restrict__ Vm, const float* __restrict__ Vc,
                       const float* __restrict__ W_comb, const float* __restrict__ Wm,
                       const float* __restrict__ Wc, const float* __restrict__ bm,
                       const float* __restrict__ bc, const float* __restrict__ vvm,
                       const float* __restrict__ gm, const float* __restrict__ vbm,
                       const float* __restrict__ rm, const float* __restrict__ vvc,
                       const float* __restrict__ gc, const float* __restrict__ vbc,
                       const float* __restrict__ rc) {
    int bidx = blockIdx.x, tid = threadIdx.x;
    if (bidx < 96) {
        for (int idx = bidx * 256 + tid; idx < 524288; idx += 96 * 256) {
            if (idx < 65536) {
                int k = idx >> 8, o = idx & 255;
                g_WihT[idx] = W_ih[o * 256 + k];
            } else if (idx < 131072) {
                int r = idx - 65536;
                int k = r >> 8, o = r & 255;
                g_WhhT[r] = W_hh[o * 256 + k];
            } else if (idx < 196608) {
                int r = idx - 131072;
                int k = r >> 8, o = r & 255;
                g_VmT[r] = Vm[o * 256 + k];
            } else if (idx < 262144) {
                int r = idx - 196608;
                int k = r >> 8, o = r & 255;
                g_VcT[r] = Vc[o * 256 + k];
            } else if (idx < 393216) {
                int r = idx - 262144;
                int k = r >> 8, o = r & 255;
                g_WcombT[r] = W_comb[o * 512 + k];
            } else {
                int r = idx - 393216;
                int o = r >> 8, k = r & 255;
                g_Wmc[r] = (o < 256) ? Wm[o * 256 + k] : Wc[(o - 256) * 256 + k];
            }
        }
    } else {
        __shared__ float red[256];
        for (int i = tid; i < B_ * 32; i += 256) g_flags[i] = 0u;
        if (tid < TDEC) g_scnt[tid] = 0u;
        if (tid == 0) {
            g_tile = 0u;
            g_tile_enc = 0u;
            g_encdone = 0u;
        }
        g_bmc[tid] = bm[tid];
        g_bmc[256 + tid] = bc[tid];
        float v = vvm[tid];
        red[tid] = v * v;
        __syncthreads();
        for (int s = 128; s > 0; s >>= 1) {
            if (tid < s) red[tid] += red[tid + s];
            __syncthreads();
        }
        float nm = sqrtf(red[0]);
        __syncthreads();
        g_wm[tid] = vvm[tid] * gm[0] / nm;
        float v2 = vvc[tid];
        red[tid] = v2 * v2;
        __syncthreads();
        for (int s = 128; s > 0; s >>= 1) {
            if (tid < s) red[tid] += red[tid + s];
            __syncthreads();
        }
        float nc = sqrtf(red[0]);
        __syncthreads();
        g_wc[tid] = vvc[tid] * gc[0] / nc;
        g_biasr[tid] = b_ih[tid] + b_hh[tid];
        if (tid == 0) {
            g_cst[0] = vbm[0] + rm[0];
            g_cst[1] = vbc[0] + rc[0];
        }
    }
}

// ---------------- token projections ----------------
__global__ __launch_bounds__(256) void k_xw(const int* __restrict__ dec,
                                            const float* __restrict__ emb) {
    __shared__ float s_x[256];
    __shared__ float s_part[1024];
    int t = blockIdx.x, b = blockIdx.y, tid = threadIdx.x;
    int tok = (t == 0) ? SOS_ : dec[b * TDEC + (t - 1)];
    s_x[tid] = __ldg(&emb[(size_t)tok * DIM + tid]);
    float y = gemv256(g_WihT, s_x, s_part) + g_biasr[tid];
    g_xw[((size_t)b * (TDEC + 1) + t) * DIM + tid] = y;
}

// ---------------- energy over [lo,hi) for batch b at step t ----------------
__device__ __forceinline__ void energy_range(int b, int lo, int hi, int t,
                                             const float* __restrict__ noise,
                                             const float* rhm, const float* rhc,
                                             const float* rwm, const float* rwc, float cm,
                                             float cc, float* out_p, float* out_ec) {
    int tid = threadIdx.x, wid = tid >> 5, lane = tid & 31;
    const size_t base = (size_t)b * TENC;
#pragma unroll 1
    for (int tt = lo + wid; tt < hi; tt += 8) {
        const float4* row4 = reinterpret_cast<const float4*>(g_encW + (base + tt) * 512);
        float4 m0 = row4[lane * 2], m1 = row4[lane * 2 + 1];
        float4 c0 = row4[64 + lane * 2], c1 = row4[64 + lane * 2 + 1];
        float mv[8] = {m0.x, m0.y, m0.z, m0.w, m1.x, m1.y, m1.z, m1.w};
        float cv[8] = {c0.x, c0.y, c0.z, c0.w, c1.x, c1.y, c1.z, c1.w};
        float am = 0.f, ac = 0.f;
#pragma unroll
        for (int j = 0; j < 8; ++j) {
            am = fmaf(tanh_hw(mv[j] + rhm[j]), rwm[j], am);
            ac = fmaf(tanh_hw(cv[j] + rhc[j]), rwc[j], ac);
        }
        am = warp_sum(am);
        ac = warp_sum(ac);
        if (lane == 0) {
            float pp =
                sigmoid_fast(am + cm + __ldg(&noise[((size_t)t * B_ + b) * TENC + tt]));
            __stcg(&out_p[tt], pp);
            __stcg(&out_ec[tt], ac + cc);
        }
    }
}

// ---------------- persistent kernel: enc GEMM + steps + vocab GEMM, co-resident ------
// 296 CTAs, occ 2/SM. CTA<128: step pipelines (b=cta&31, q=cta>>5: q0 post, q1/q2/q3
// energy thirds + hVc/uch/hVm). CTA>=128: enc tiles then vocab tiles. Everyone drains
// the vocab queue at the end. Safe at occ 1 too (resident set can drain all queues).
__global__ __launch_bounds__(256, 2) void k_main(
    const float* __restrict__ enc, const float* __restrict__ h0,
    const float* __restrict__ noise, const float* __restrict__ Wproj,
    const float* __restrict__ bproj, float* __restrict__ out) {
    __shared__ SmU su;
    __shared__ int s_idx;

    int tid = threadIdx.x, cta = blockIdx.x;

    if (cta < 128) {
        int b = cta & 31, q = cta >> 5;
        int lane = tid & 31;
        int a0 = lane * 8;

        if (q == 0) {
            // ---- POST ----
            su.st.h[tid] = h0[b * DIM + tid];
            su.st.alpha[tid] = (tid == 0) ? 1.0f : 0.0f;
            su.st.alpha[256 + tid] = 0.0f;
            float yh = gemv256(g_WhhT, su.st.h, su.st.part);
            float hn = tanh_fast(yh + __ldg(&g_xw[((size_t)b * (TDEC + 1)) * DIM + tid]));
            __syncthreads();
            su.st.h[tid] = hn;
            __stcg(&g_h[0][b * DIM + tid], hn);
            publish_exch(FLG(b, 0), 1u);

#pragma unroll 1
            for (int t = 0; t < TDEC; ++t) {
                int par = t & 1;
                if (t < TDEC - 1) {
                    float yh2 = gemv256(g_WhhT, su.st.h, su.st.part);
                    float hn2 = tanh_fast(
                        yh2 + __ldg(&g_xw[((size_t)b * (TDEC + 1) + t + 1) * DIM + tid]));
                    __syncthreads();
                    su.st.h[tid] = hn2;
                    __stcg(&g_h[1 - par][b * DIM + tid], hn2);
                    publish_exch(FLG(b, 0), (unsigned)(t + 2));
                }
                spin_cta_multi(FLG(b, 0), 4, 3, (unsigned)(t + 1));

                int j0 = 2 * tid, j1 = 2 * tid + 1;
                float p0 = __ldcg(&g_p[par][b * TENC + j0]);
                float p1 = __ldcg(&g_p[par][b * TENC + j1]);
                float l0 = __logf(fminf(fmaxf(1.0f - p0, 1e-10f), 1.0f));
                float l1 = __logf(fminf(fmaxf(1.0f - p1, 1e-10f), 1.0f));
                float eP = pair_excl(l0 + l1, su.st.w8);
                float cp0 = __expf(eP);
                float cp1 = __expf(eP + l0);
                float A0 = su.st.alpha[j0], A1 = su.st.alpha[j1];
                float r0 = __fdividef(A0, fmaxf(cp0, 1e-10f));
                float r1 = __fdividef(A1, fmaxf(cp1, 1e-10f));
                float eS = pair_excl(r0 + r1, su.st.w8);
                float na0 = p0 * cp0 * (eS + r0);
                float na1 = p1 * cp1 * (eS + r0 + r1);
                su.st.alpha[j0] = na0;
                su.st.alpha[j1] = na1;

                float e0 = __ldcg(&g_ecb[par][b * TENC + j0]);
                float e1 = __ldcg(&g_ecb[par][b * TENC + j1]);
                float mx = max512(fmaxf(e0, e1), su.st.w8);
                float eu0 = __expf(e0 - mx), eu1 = __expf(e1 - mx);
                su.st.eu[j0] = eu0;
                su.st.eu[j1] = eu1;
                __syncthreads();
                float d0 = 0.0f, d1 = 0.0f;
#pragma unroll
                for (int k = 0; k < 8; ++k) {
                    int q0i = j0 - k, q1i = j1 - k;
                    if (q0i >= 0) d0 += su.st.eu[q0i];
                    if (q1i >= 0) d1 += su.st.eu[q1i];
                }
                su.st.ratio[j0] = __fdividef(na0, fmaxf(d0, 1e-10f));
                su.st.ratio[j1] = __fdividef(na1, fmaxf(d1, 1e-10f));
                __syncthreads();
                float b0 = 0.0f, b1 = 0.0f;
#pragma unroll
                for (int k = 0; k < 8; ++k) {
                    int q0i = j0 + k, q1i = j1 + k;
                    if (q0i < TENC) b0 += su.st.ratio[q0i];
                    if (q1i < TENC) b1 += su.st.ratio[q1i];
                }
                su.st.beta[j0] = eu0 * b0;
                su.st.beta[j1] = eu1 * b1;
                __syncthreads();

                {
                    int jj = tid & 63, tq4 = tid >> 6;
                    const float4* ep = reinterpret_cast<const float4*>(enc) +
                                       (size_t)(b * TENC + tq4 * 128) * (DIM / 4) + jj;
                    float4 acc = make_float4(0.f, 0.f, 0.f, 0.f);
#pragma unroll 4
                    for (int ttt = 0; ttt < 128; ++ttt) {
                        float f = su.st.beta[tq4 * 128 + ttt];
                        float4 e4 = ep[(size_t)ttt * 64];
                        acc.x = fmaf(f, e4.x, acc.x);
                        acc.y = fmaf(f, e4.y, acc.y);
                        acc.z = fmaf(f, e4.z, acc.z);
                        acc.w = fmaf(f, e4.w, acc.w);
                    }
                    reinterpret_cast<float4*>(su.st.part)[tq4 * 64 + jj] = acc;
                }
                __syncthreads();
                su.st.ctx[tid] = su.st.part[tid] + su.st.part[256 + tid] +
                                 su.st.part[512 + tid] + su.st.part[768 + tid];

                float av = gemv256(g_WcombT, su.st.ctx, su.st.part);
                spin_cta(FLG(b, 3), (unsigned)(t + 1));
                float at = tanh_fast(av + __ldcg(&g_uch[par][b * DIM + tid]));
                __stcg(&g_attn[((size_t)t * B_ + b) * DIM + tid], at);
                __threadfence();
                __syncthreads();
                if (tid == 0) atomicAdd(&g_scnt[t], 1u);
            }
        } else {
            // ---- WORKERS ----
            int lo = (q == 1) ? 0 : (q == 2) ? 171 : 342;
            int hi = (q == 1) ? 171 : (q == 2) ? 342 : 512;
            float cm = g_cst[0], cc = g_cst[1];
            float rwm[8], rwc[8];
#pragma unroll
            for (int j = 0; j < 8; ++j) {
                rwm[j] = __ldg(&g_wm[a0 + j]);
                rwc[j] = __ldg(&g_wc[a0 + j]);
            }
            if (q == 1) {
                spin_cta(FLG(b, 0), 1u);
                su.st.ctx[tid] = __ldcg(&g_h[0][b * DIM + tid]);
                float yc = gemv256(g_VcT, su.st.ctx, su.st.part);
                __stcg(&g_hVc[0][b * DIM + tid], yc);
                publish_exch(FLG(b, 2), 1u);
            } else if (q == 3) {
                spin_cta(FLG(b, 0), 1u);
                su.st.ctx[tid] = __ldcg(&g_h[0][b * DIM + tid]);
                float ym = gemv256(g_VmT, su.st.ctx, su.st.part);
                __stcg(&g_hVm[0][b * DIM + tid], ym);
                publish_exch(FLG(b, 1), 1u);
            }
            // encoder projection must be complete before any energy read
            spin_cta(&g_encdone, (unsigned)NTILE_E);
            __threadfence();

#pragma unroll 1
            for (int t = 0; t < TDEC; ++t) {
                int par = t & 1;
                spin_cta_multi(FLG(b, 0), 1, 2, (unsigned)(t + 1));
                float rhm[8], rhc[8];
                {
                    const float* hm = g_hVm[par] + b * DIM + a0;
                    const float* hc = g_hVc[par] + b * DIM + a0;
                    float4 v0 = __ldcg(reinterpret_cast<const float4*>(hm));
                    float4 v1 = __ldcg(reinterpret_cast<const float4*>(hm + 4));
                    rhm[0] = v0.x; rhm[1] = v0.y; rhm[2] = v0.z; rhm[3] = v0.w;
                    rhm[4] = v1.x; rhm[5] = v1.y; rhm[6] = v1.z; rhm[7] = v1.w;
                    float4 w0 = __ldcg(reinterpret_cast<const float4*>(hc));
                    float4 w1 = __ldcg(reinterpret_cast<const float4*>(hc + 4));
                    rhc[0] = w0.x; rhc[1] = w0.y; rhc[2] = w0.z; rhc[3] = w0.w;
                    rhc[4] = w1.x; rhc[5] = w1.y; rhc[6] = w1.z; rhc[7] = w1.w;
                }
                energy_range(b, lo, hi, t, noise, rhm, rhc, rwm, rwc, cm, cc,
                             g_p[par] + b * TENC, g_ecb[par] + b * TENC);
                publish_exch(FLG(b, 3 + q), (unsigned)(t + 1));
                if (q == 2) {
                    su.st.ctx[tid] = __ldcg(&g_h[par][b * DIM + tid]);
                    float u = gemv256(g_WcombT + 256 * 256, su.st.ctx, su.st.part);
                    __stcg(&g_uch[par][b * DIM + tid], u);
                    publish_exch(FLG(b, 3), (unsigned)(t + 1));
                } else if (q == 1 && t < TDEC - 1) {
                    spin_cta(FLG(b, 0), (unsigned)(t + 2));
                    su.st.ctx[tid] = __ldcg(&g_h[1 - par][b * DIM + tid]);
                    float yc = gemv256(g_VcT, su.st.ctx, su.st.part);
                    __stcg(&g_hVc[1 - par][b * DIM + tid], yc);
                    publish_exch(FLG(b, 2), (unsigned)(t + 2));
                } else if (q == 3 && t < TDEC - 1) {
                    spin_cta(FLG(b, 0), (unsigned)(t + 2));
                    su.st.ctx[tid] = __ldcg(&g_h[1 - par][b * DIM + tid]);
                    float ym = gemv256(g_VmT, su.st.ctx, su.st.part);
                    __stcg(&g_hVm[1 - par][b * DIM + tid], ym);
                    publish_exch(FLG(b, 1), (unsigned)(t + 2));
                }
            }
        }
    } else {
        // ---- GEMM workers: encoder projection first ----
        for (;;) {
            __syncthreads();
            if (tid == 0) s_idx = (int)atomicAdd(&g_tile_enc, 1u);
            __syncthreads();
            int idx = s_idx;
            if (idx >= NTILE_E) break;
            gemm_tile64<false, false>(enc, g_Wmc, g_bmc, g_encW, (idx >> 2) * 64,
                                      (idx & 3) * 128, 512, &su.gm);
            __threadfence();
            __syncthreads();
            if (tid == 0) atomicAdd(&g_encdone, 1u);
        }
    }

    // ---- everyone: work-steal vocab GEMM, tiles gated on step completion ----
    for (;;) {
        __syncthreads();
        if (tid == 0) s_idx = (int)atomicAdd(&g_tile, 1u);
        __syncthreads();
        int idx = s_idx;
        if (idx >= NTILE_V) break;
        int m = idx / (VOCAB_ / 128);
        int n = idx - m * (VOCAB_ / 128);
        if (tid == 0) {
            const volatile unsigned* f = &g_scnt[2 * m + 1];
            while (*f < 32u) __nanosleep(256);
        }
        __syncthreads();
        __threadfence();
        gemm_tile64<true, true>(g_attn, Wproj, bproj, out, m * 64, n * 128, VOCAB_,
                                &su.gm);
    }
}

// ---------------- launch ----------------
extern "C" void kernel_launch(void* const* d_in, const int* in_sizes, int n_in, void* d_out,
                              int out_size) {
    (void)in_sizes;
    (void)n_in;
    (void)out_size;
    const float* enc = (const float*)d_in[0];
    const int* dec = (const int*)d_in[1];
    const float* h0 = (const float*)d_in[2];
    const float* noise = (const float*)d_in[3];
    const float* emb = (const float*)d_in[4];
    const float* W_ih = (const float*)d_in[5];
    const float* b_ih = (const float*)d_in[6];
    const float* W_hh = (const float*)d_in[7];
    const float* b_hh = (const float*)d_in[8];
    const float* Wm = (const float*)d_in[9];
    const float* Vm = (const float*)d_in[10];
    const float* bm = (const float*)d_in[11];
    const float* vvm = (const float*)d_in[12];
    const float* gm = (const float*)d_in[13];
    const float* vbm = (const float*)d_in[14];
    const float* rm = (const float*)d_in[15];
    const float* Wc = (const float*)d_in[16];
    const float* Vc = (const float*)d_in[17];
    const float* bc = (const float*)d_in[18];
    const float* vvc = (const float*)d_in[19];
    const float* gc = (const float*)d_in[20];
    const float* vbc = (const float*)d_in[21];
    const float* rc = (const float*)d_in[22];
    const float* W_comb = (const float*)d_in[23];
    const float* W_proj = (const float*)d_in[24];
    const float* b_proj = (const float*)d_in[25];
    float* out = (float*)d_out;

    k_init<<<97, 256>>>(W_ih, b_ih, W_hh, b_hh, Vm, Vc, W_comb, Wm, Wc, bm, bc, vvm, gm,
                        vbm, rm, vvc, gc, vbc, rc);
    k_xw<<<dim3(TDEC + 1, B_), 256>>>(dec, emb);
    k_main<<<296, 256>>>(enc, h0, noise, W_proj, b_proj, out);
}